// round 8
// baseline (speedup 1.0000x reference)
#include <cuda_runtime.h>
#include <cuda_fp16.h>
#include <math_constants.h>
#include <cstdint>

#define Bq 4
#define Tq 1024
#define Cq 16
#define Dq 256
#define NHEADS (Bq*Cq)
#define MTOT (Bq*Tq*Cq)

__device__ __align__(128) __half g_xb[(size_t)MTOT * Dq];
__device__ __align__(128) __half g_wb[3 * Dq * Dq];
__device__ __align__(128) unsigned char g_q8 [(size_t)NHEADS * Tq * Dq];
__device__ __align__(128) unsigned char g_k8 [(size_t)NHEADS * Tq * Dq];
__device__ __align__(128) unsigned char g_v8 [(size_t)NHEADS * Tq * Dq];
__device__ __align__(128) unsigned char g_vt8[(size_t)NHEADS * Dq * Tq];
__device__ __align__(128) unsigned char g_mt[NHEADS * Tq];

static __device__ __forceinline__ unsigned packh(float a, float b) {
    __half2 h = __floats2half2_rn(a, b);
    return *reinterpret_cast<unsigned*>(&h);
}
static __device__ __forceinline__ float2 unph(unsigned u) {
    __half2 h = *reinterpret_cast<__half2*>(&u);
    return __half22float2(h);
}
static __device__ __forceinline__ unsigned short cvt8x2(float hi, float lo) {
    unsigned short r;
    asm("cvt.rn.satfinite.e4m3x2.f32 %0, %1, %2;" : "=h"(r) : "f"(hi), "f"(lo));
    return r;
}
static __device__ __forceinline__ void mma_f16_f16(
    unsigned& d0, unsigned& d1,
    unsigned a0, unsigned a1, unsigned a2, unsigned a3,
    unsigned b0, unsigned b1)
{
    asm volatile(
        "mma.sync.aligned.m16n8k16.row.col.f16.f16.f16.f16 "
        "{%0,%1}, {%2,%3,%4,%5}, {%6,%7}, {%0,%1};\n"
        : "+r"(d0), "+r"(d1)
        : "r"(a0), "r"(a1), "r"(a2), "r"(a3), "r"(b0), "r"(b1));
}
static __device__ __forceinline__ void mma_fp8(
    float& d0, float& d1, float& d2, float& d3,
    unsigned a0, unsigned a1, unsigned a2, unsigned a3,
    unsigned b0, unsigned b1)
{
    asm volatile(
        "mma.sync.aligned.m16n8k32.row.col.f32.e4m3.e4m3.f32 "
        "{%0,%1,%2,%3}, {%4,%5,%6,%7}, {%8,%9}, {%0,%1,%2,%3};\n"
        : "+f"(d0), "+f"(d1), "+f"(d2), "+f"(d3)
        : "r"(a0), "r"(a1), "r"(a2), "r"(a3), "r"(b0), "r"(b1));
}
static __device__ __forceinline__ void ldsm_x4(
    unsigned& r0, unsigned& r1, unsigned& r2, unsigned& r3, unsigned addr)
{
    asm volatile("ldmatrix.sync.aligned.m8n8.x4.shared.b16 {%0,%1,%2,%3}, [%4];"
        : "=r"(r0), "=r"(r1), "=r"(r2), "=r"(r3) : "r"(addr));
}

#define CPA16(d, s) asm volatile("cp.async.cg.shared.global [%0], [%1], 16;" :: "r"(d), "l"(s))
#define CP_COMMIT() asm volatile("cp.async.commit_group;")
#define CP_WAIT(n)  asm volatile("cp.async.wait_group %0;" :: "n"(n))
#define STS16(a, v) asm volatile("st.shared.u16 [%0], %1;" :: "r"(a), "h"(v))

// ---------------------------------------------------------------------------
__global__ void conv_x_kernel(const float* __restrict__ x)
{
    int i = blockIdx.x * blockDim.x + threadIdx.x;
    const float4 v = ((const float4*)x)[i];
    ((uint2*)g_xb)[i] = make_uint2(packh(v.x, v.y), packh(v.z, v.w));
}
__global__ void conv_w_kernel(const float* __restrict__ wq,
                              const float* __restrict__ wk,
                              const float* __restrict__ wv)
{
    int i = blockIdx.x * blockDim.x + threadIdx.x;
    g_wb[i]          = __float2half(wq[i]);
    g_wb[i + 65536]  = __float2half(wk[i]);
    g_wb[i + 131072] = __float2half(wv[i]);
}
__global__ void conv_m_kernel(const unsigned char* __restrict__ xmask)
{
    int i = blockIdx.x * blockDim.x + threadIdx.x;
    int h = i >> 10, t = i & 1023;
    int b = h >> 4,  c = h & 15;
    g_mt[i] = xmask[(size_t)((b << 10) + t) * Cq + c];
}
// transpose V: g_vt8[h][d][t] = g_v8[h][t][d]
__global__ void transpose_v_kernel()
{
    __shared__ unsigned char ts[64 * 80];
    const int tid = threadIdx.x;
    const int t0 = blockIdx.x * 64, d0 = blockIdx.y * 64, h = blockIdx.z;
    const unsigned char* src = g_v8 + ((size_t)h * Tq + t0) * Dq + d0;
    {
        int r = tid >> 2, cs = tid & 3;
        *(uint4*)&ts[r * 80 + cs * 16] = *(const uint4*)(src + (size_t)r * Dq + cs * 16);
    }
    __syncthreads();
    {
        int dd = tid >> 2, tseg = tid & 3;
        unsigned rr[4];
#pragma unroll
        for (int wd = 0; wd < 4; ++wd) {
            unsigned v = 0;
#pragma unroll
            for (int j = 0; j < 4; ++j)
                v |= (unsigned)ts[(tseg * 16 + wd * 4 + j) * 80 + dd] << (8 * j);
            rr[wd] = v;
        }
        *(uint4*)(g_vt8 + ((size_t)h * Dq + d0 + dd) * Tq + t0 + tseg * 16) =
            make_uint4(rr[0], rr[1], rr[2], rr[3]);
    }
}

// ---------------------------------------------------------------------------
// QKV projection (R6 mainloop, f16 HMMA/f16acc), epilogue emits e4m3.
// ---------------------------------------------------------------------------
#define QX_OFF 0u
#define QW0_OFF 67584u
#define QW1_OFF 137216u
#define QK_SMEM (137216 + 69632)

__global__ __launch_bounds__(256, 1) void qkv_mma_kernel(
    const int*   __restrict__ pos,
    const float* __restrict__ pe,
    const float* __restrict__ bq,
    const float* __restrict__ bk,
    const float* __restrict__ bv)
{
    extern __shared__ char sm[];
    const unsigned su = (unsigned)__cvta_generic_to_shared(sm);
    const int tid = threadIdx.x, w = tid >> 5, lane = tid & 31;
    const int q = lane & 3, lr = lane >> 2, g = lane >> 3, r8 = lane & 7;
    const int wm = w >> 2, wn = w & 3;
    const int mat = blockIdx.x;
    const int m0  = blockIdx.y * 128;

    const __half* xb = g_xb + (size_t)m0 * Dq;
#pragma unroll
    for (int it = 0; it < 16; ++it) {
        int idx = it * 256 + tid;
        int row = idx >> 5, ch = idx & 31;
        CPA16(su + QX_OFF + (unsigned)(row * 528 + ch * 16), xb + row * Dq + ch * 8);
    }
    const __half* wb = g_wb + mat * 65536;
#pragma unroll
    for (int it = 0; it < 16; ++it) {
        int idx = it * 256 + tid;
        int row = idx >> 4, ch = idx & 15;
        CPA16(su + QW0_OFF + (unsigned)(row * 272 + ch * 16), wb + row * Dq + ch * 8);
    }
    CP_COMMIT();
#pragma unroll
    for (int it = 0; it < 16; ++it) {
        int idx = it * 256 + tid;
        int row = idx >> 4, ch = idx & 15;
        CPA16(su + QW1_OFF + (unsigned)(row * 272 + ch * 16), wb + row * Dq + 128 + ch * 8);
    }
    CP_COMMIT();

    unsigned acc[4][8][2];
#pragma unroll
    for (int mt = 0; mt < 4; ++mt)
#pragma unroll
        for (int nt = 0; nt < 8; ++nt) { acc[mt][nt][0] = 0u; acc[mt][nt][1] = 0u; }

    const unsigned a_base = su + QX_OFF +
        (unsigned)((wm * 64 + (g & 1) * 8 + r8) * 528 + ((g >> 1) * 8) * 2);
    const unsigned b_base = su + QW0_OFF +
        (unsigned)((wn * 64 + (g >> 1) * 8 + r8) * 272 + ((g & 1) * 8) * 2);

#pragma unroll
    for (int ph = 0; ph < 2; ++ph) {
        if (ph == 0) { CP_WAIT(1); } else { CP_WAIT(0); }
        __syncthreads();
        const unsigned ab = a_base + (unsigned)ph * 256u;
        const unsigned bb = b_base + (unsigned)ph * (QW1_OFF - QW0_OFF);
#pragma unroll
        for (int kk = 0; kk < 8; ++kk) {
            unsigned af[4][4];
#pragma unroll
            for (int mt = 0; mt < 4; ++mt)
                ldsm_x4(af[mt][0], af[mt][1], af[mt][2], af[mt][3],
                        ab + (unsigned)(mt * 16 * 528) + kk * 32);
#pragma unroll
            for (int nt = 0; nt < 4; ++nt) {
                unsigned b0, b1, b2, b3;
                ldsm_x4(b0, b1, b2, b3, bb + (unsigned)(nt * 16 * 272) + kk * 32);
#pragma unroll
                for (int mt = 0; mt < 4; ++mt) {
                    mma_f16_f16(acc[mt][2*nt][0],   acc[mt][2*nt][1],
                                af[mt][0], af[mt][1], af[mt][2], af[mt][3], b0, b1);
                    mma_f16_f16(acc[mt][2*nt+1][0], acc[mt][2*nt+1][1],
                                af[mt][0], af[mt][1], af[mt][2], af[mt][3], b2, b3);
                }
            }
        }
    }

    const float* bias = (mat == 0) ? bq : (mat == 1) ? bk : bv;
    unsigned char* outp = (mat == 0) ? g_q8 : (mat == 1) ? g_k8 : g_v8;

#pragma unroll
    for (int mt = 0; mt < 4; ++mt) {
        const int tokA = m0 + wm * 64 + mt * 16 + lr;
        const int tokB = tokA + 8;
        const int bA = tokA >> 14, tA = (tokA >> 4) & (Tq-1), cA = tokA & (Cq-1);
        const int bB = tokB >> 14, tB = (tokB >> 4) & (Tq-1), cB = tokB & (Cq-1);
        unsigned char* rowA = outp + ((size_t)(bA * Cq + cA) * Tq + tA) * Dq;
        unsigned char* rowB = outp + ((size_t)(bB * Cq + cB) * Tq + tB) * Dq;
        int pA = 0, pB = 0;
        if (mat < 2) { pA = pos[tokA]; pB = pos[tokB]; }
#pragma unroll
        for (int nt = 0; nt < 8; ++nt) {
            const int col = wn * 64 + nt * 8 + 2 * q;
            const float2 b2 = *(const float2*)(bias + col);
            float2 va = unph(acc[mt][nt][0]);
            float2 vb = unph(acc[mt][nt][1]);
            float v0 = va.x + b2.x, v1 = va.y + b2.y;
            float v2 = vb.x + b2.x, v3 = vb.y + b2.y;
            if (mat < 2) {
                const float2 csA = *(const float2*)(pe + (size_t)pA * Dq + col);
                const float2 csB = *(const float2*)(pe + (size_t)pB * Dq + col);
                float r0 = v0 * csA.x - v1 * csA.y;
                v1 = v0 * csA.y + v1 * csA.x; v0 = r0;
                float r2 = v2 * csB.x - v3 * csB.y;
                v3 = v2 * csB.y + v3 * csB.x; v2 = r2;
            }
            *(unsigned short*)&rowA[col] = cvt8x2(v1, v0);
            *(unsigned short*)&rowB[col] = cvt8x2(v3, v2);
        }
    }
}

// ---------------------------------------------------------------------------
// FP8 flash attention + frozen-max softmax + fused residual/LS/LN.
// CTA = (head, 128 q-rows); 8 warps x 16 rows; K tiles 64, 16 iters, 3 stages.
// ---------------------------------------------------------------------------
#define KSTR 272
#define VSTR 80
#define KTB (64 * KSTR)            // 17408
#define STAGE (KTB + 256 * VSTR)   // 37888
#define Q_OFF  (3 * STAGE)         // 113664
#define P_OFF  (Q_OFF + 128 * KSTR)    // 148480
#define QM_OFF (P_OFF + 8 * 1280)      // 158720
#define KM_OFF (QM_OFF + 128)          // 158848
#define ATTN_SMEM (KM_OFF + 192 + 64)

__global__ __launch_bounds__(256, 1) void attn_fp8_kernel(
    const float* __restrict__ x,
    const float* __restrict__ lng,
    const float* __restrict__ lnb,
    const float* __restrict__ lsg,
    float* __restrict__ out)
{
    extern __shared__ char smraw[];
    const unsigned char* sQm = (const unsigned char*)(smraw + QM_OFF);
    const unsigned char* sKmB = (const unsigned char*)(smraw + KM_OFF);
    const unsigned su = (unsigned)__cvta_generic_to_shared(smraw);

    const int tid  = threadIdx.x;
    const int w    = tid >> 5;
    const int lane = tid & 31;
    const int q    = lane & 3;
    const int lr   = lane >> 2;
    const int g    = lane >> 3;
    const int r8   = lane & 7;

    const int h  = blockIdx.y;
    const int b  = h >> 4, c = h & 15;
    const int q0 = blockIdx.x * 128;

    const unsigned char* qg  = g_q8 + ((size_t)h * Tq + q0) * Dq;
    const unsigned char* kg  = g_k8 + (size_t)h * Tq * Dq;
    const unsigned char* vtg = g_vt8 + (size_t)h * Dq * Tq;
    const unsigned char* mg  = g_mt + h * Tq;

    // ---- stage Q (128x256 B) + q-mask ----
#pragma unroll
    for (int it = 0; it < 8; ++it) {
        int idx = it * 256 + tid;
        int row = idx >> 4, sg = idx & 15;
        CPA16(su + Q_OFF + (unsigned)(row * KSTR + sg * 16), qg + row * Dq + sg * 16);
    }
    if (tid < 8) CPA16(su + QM_OFF + tid * 16, mg + q0 + tid * 16);
    CP_COMMIT(); CP_WAIT(0);
    __syncthreads();

    unsigned qf[8][4];
    const unsigned qa = su + Q_OFF +
        (unsigned)((w * 16 + (g & 1) * 8 + r8) * KSTR + (g >> 1) * 16);
#pragma unroll
    for (int kk = 0; kk < 8; ++kk)
        ldsm_x4(qf[kk][0], qf[kk][1], qf[kk][2], qf[kk][3], qa + kk * 32);
    const int qmA = sQm[w * 16 + lr];
    const int qmB = sQm[w * 16 + lr + 8];

    auto issue = [&](int kt) {
        const int st = kt % 3;
        const unsigned sb = su + st * STAGE;
        const int k0 = kt * 64;
#pragma unroll
        for (int it = 0; it < 4; ++it) {
            int idx = it * 256 + tid;
            int row = idx >> 4, sg = idx & 15;
            CPA16(sb + (unsigned)(row * KSTR + sg * 16),
                  kg + (size_t)(k0 + row) * Dq + sg * 16);
        }
#pragma unroll
        for (int it = 0; it < 4; ++it) {
            int idx = it * 256 + tid;
            int row = idx >> 2, sg = idx & 3;
            CPA16(sb + KTB + (unsigned)(row * VSTR + sg * 16),
                  vtg + (size_t)row * Tq + k0 + sg * 16);
        }
        if (tid < 4) CPA16(su + KM_OFF + st * 64 + tid * 16, mg + k0 + tid * 16);
    };
    issue(0); CP_COMMIT();
    issue(1); CP_COMMIT();

    float oacc[32][4];
#pragma unroll
    for (int nt = 0; nt < 32; ++nt)
#pragma unroll
        for (int j = 0; j < 4; ++j) oacc[nt][j] = 0.f;
    float lsumA = 0.f, lsumB = 0.f, mUA = 0.f, mUB = 0.f;

    for (int kt = 0; kt < 16; ++kt) {
        CP_WAIT(1);
        __syncthreads();
        const int st = kt % 3;
        const unsigned kb = su + st * STAGE;
        const unsigned vb = kb + KTB;
        const unsigned char* km = sKmB + st * 64;

        // ---- S = Q K^T (fp8, f32 acc) ----
        float sacc[8][4];
#pragma unroll
        for (int nf = 0; nf < 8; ++nf)
#pragma unroll
            for (int j = 0; j < 4; ++j) sacc[nf][j] = 0.f;
#pragma unroll
        for (int kk = 0; kk < 8; ++kk) {
#pragma unroll
            for (int ng = 0; ng < 4; ++ng) {
                unsigned b0, b1, b2, b3;
                ldsm_x4(b0, b1, b2, b3,
                        kb + (unsigned)((ng * 16 + (g >> 1) * 8 + r8) * KSTR
                                        + (g & 1) * 16) + kk * 32);
                mma_fp8(sacc[2*ng][0], sacc[2*ng][1], sacc[2*ng][2], sacc[2*ng][3],
                        qf[kk][0], qf[kk][1], qf[kk][2], qf[kk][3], b0, b1);
                mma_fp8(sacc[2*ng+1][0], sacc[2*ng+1][1], sacc[2*ng+1][2], sacc[2*ng+1][3],
                        qf[kk][0], qf[kk][1], qf[kk][2], qf[kk][3], b2, b3);
            }
        }

        // ---- frozen max from kt 0 ----
        if (kt == 0) {
            float tA = -CUDART_INF_F, tB = -CUDART_INF_F;
#pragma unroll
            for (int nf = 0; nf < 8; ++nf) {
                const int cc = nf * 8 + 2 * q;
                const int k0m = km[cc], k1m = km[cc + 1];
                float s0 = (qmA | k0m) ? -CUDART_INF_F : sacc[nf][0] * 0.0625f;
                float s1 = (qmA | k1m) ? -CUDART_INF_F : sacc[nf][1] * 0.0625f;
                float s2 = (qmB | k0m) ? -CUDART_INF_F : sacc[nf][2] * 0.0625f;
                float s3 = (qmB | k1m) ? -CUDART_INF_F : sacc[nf][3] * 0.0625f;
                tA = fmaxf(tA, fmaxf(s0, s1));
                tB = fmaxf(tB, fmaxf(s2, s3));
            }
            tA = fmaxf(tA, __shfl_xor_sync(0xffffffffu, tA, 1));
            tA = fmaxf(tA, __shfl_xor_sync(0xffffffffu, tA, 2));
            tB = fmaxf(tB, __shfl_xor_sync(0xffffffffu, tB, 1));
            tB = fmaxf(tB, __shfl_xor_sync(0xffffffffu, tB, 2));
            mUA = (tA < -1e30f) ? 0.f : tA;
            mUB = (tB < -1e30f) ? 0.f : tB;
        }

        // ---- exp + pack e4m3 + store P to per-warp smem ----
        const unsigned base_p = su + P_OFF + (unsigned)(w * 1280);
#pragma unroll
        for (int nf = 0; nf < 8; ++nf) {
            const int cc = nf * 8 + 2 * q;
            const int k0m = km[cc], k1m = km[cc + 1];
            float p00 = (qmA | k0m) ? 0.f : __expf(sacc[nf][0] * 0.0625f - mUA);
            float p01 = (qmA | k1m) ? 0.f : __expf(sacc[nf][1] * 0.0625f - mUA);
            float p10 = (qmB | k0m) ? 0.f : __expf(sacc[nf][2] * 0.0625f - mUB);
            float p11 = (qmB | k1m) ? 0.f : __expf(sacc[nf][3] * 0.0625f - mUB);
            lsumA += p00 + p01;
            lsumB += p10 + p11;
            STS16(base_p + (unsigned)(lr * 80 + cc), cvt8x2(p01, p00));
            STS16(base_p + (unsigned)((lr + 8) * 80 + cc), cvt8x2(p11, p10));
        }
        __syncwarp();
        unsigned pa[2][4];
        const unsigned pab = base_p + (unsigned)(((g & 1) * 8 + r8) * 80 + (g >> 1) * 16);
        ldsm_x4(pa[0][0], pa[0][1], pa[0][2], pa[0][3], pab);
        ldsm_x4(pa[1][0], pa[1][1], pa[1][2], pa[1][3], pab + 32);

        // ---- O += P V (fp8, f32 acc) ----
#pragma unroll
        for (int kkv = 0; kkv < 2; ++kkv) {
#pragma unroll
            for (int dg = 0; dg < 16; ++dg) {
                unsigned v0, v1, v2, v3;
                ldsm_x4(v0, v1, v2, v3,
                        vb + (unsigned)((dg * 16 + (g >> 1) * 8 + r8) * VSTR
                                        + (g & 1) * 16) + kkv * 32);
                mma_fp8(oacc[2*dg][0], oacc[2*dg][1], oacc[2*dg][2], oacc[2*dg][3],
                        pa[kkv][0], pa[kkv][1], pa[kkv][2], pa[kkv][3], v0, v1);
                mma_fp8(oacc[2*dg+1][0], oacc[2*dg+1][1], oacc[2*dg+1][2], oacc[2*dg+1][3],
                        pa[kkv][0], pa[kkv][1], pa[kkv][2], pa[kkv][3], v2, v3);
            }
        }
        if (kt + 2 < 16) issue(kt + 2);
        CP_COMMIT();
    }

    // ---- epilogue: residual + LayerScale + LayerNorm (two-pass) ----
    lsumA += __shfl_xor_sync(0xffffffffu, lsumA, 1);
    lsumA += __shfl_xor_sync(0xffffffffu, lsumA, 2);
    lsumB += __shfl_xor_sync(0xffffffffu, lsumB, 1);
    lsumB += __shfl_xor_sync(0xffffffffu, lsumB, 2);
    const float invA = (lsumA > 0.f) ? (1.f / lsumA) : 0.f;
    const float invB = (lsumB > 0.f) ? (1.f / lsumB) : 0.f;

    const int gtA = q0 + w * 16 + lr;
    const int gtB = gtA + 8;
    const size_t miA = (size_t)(b * Tq + gtA) * Cq + c;
    const size_t miB = (size_t)(b * Tq + gtB) * Cq + c;
    const float* xA = x + miA * Dq;
    const float* xB = x + miB * Dq;

    float sumA = 0.f, ssqA = 0.f, sumB = 0.f, ssqB = 0.f;
#pragma unroll
    for (int nt = 0; nt < 32; ++nt) {
        const int cc = nt * 8 + 2 * q;
        const float2 g2 = *(const float2*)(lsg + cc);
        const float2 xa = *(const float2*)(xA + cc);
        const float2 xb2 = *(const float2*)(xB + cc);
        float y0 = xa.x  + g2.x * (oacc[nt][0] * invA);
        float y1 = xa.y  + g2.y * (oacc[nt][1] * invA);
        float y2 = xb2.x + g2.x * (oacc[nt][2] * invB);
        float y3 = xb2.y + g2.y * (oacc[nt][3] * invB);
        sumA += y0 + y1;  ssqA += y0 * y0 + y1 * y1;
        sumB += y2 + y3;  ssqB += y2 * y2 + y3 * y3;
    }
    sumA += __shfl_xor_sync(0xffffffffu, sumA, 1);
    sumA += __shfl_xor_sync(0xffffffffu, sumA, 2);
    ssqA += __shfl_xor_sync(0xffffffffu, ssqA, 1);
    ssqA += __shfl_xor_sync(0xffffffffu, ssqA, 2);
    sumB += __shfl_xor_sync(0xffffffffu, sumB, 1);
    sumB += __shfl_xor_sync(0xffffffffu, sumB, 2);
    ssqB += __shfl_xor_sync(0xffffffffu, ssqB, 1);
    ssqB += __shfl_xor_sync(0xffffffffu, ssqB, 2);

    const float muA = sumA * (1.f / 256.f);
    const float muB = sumB * (1.f / 256.f);
    const float rsA = rsqrtf(ssqA * (1.f / 256.f) - muA * muA + 1e-5f);
    const float rsB = rsqrtf(ssqB * (1.f / 256.f) - muB * muB + 1e-5f);

    float* oA = out + miA * Dq;
    float* oB = out + miB * Dq;
#pragma unroll
    for (int nt = 0; nt < 32; ++nt) {
        const int cc = nt * 8 + 2 * q;
        const float2 g2 = *(const float2*)(lsg + cc);
        const float2 gg = *(const float2*)(lng + cc);
        const float2 bb = *(const float2*)(lnb + cc);
        const float2 xa = *(const float2*)(xA + cc);
        const float2 xb2 = *(const float2*)(xB + cc);
        float y0 = xa.x  + g2.x * (oacc[nt][0] * invA);
        float y1 = xa.y  + g2.y * (oacc[nt][1] * invA);
        float y2 = xb2.x + g2.x * (oacc[nt][2] * invB);
        float y3 = xb2.y + g2.y * (oacc[nt][3] * invB);
        float2 r0, r1;
        r0.x = (y0 - muA) * rsA * gg.x + bb.x;
        r0.y = (y1 - muA) * rsA * gg.y + bb.y;
        r1.x = (y2 - muB) * rsB * gg.x + bb.x;
        r1.y = (y3 - muB) * rsB * gg.y + bb.y;
        *(float2*)(oA + cc) = r0;
        *(float2*)(oB + cc) = r1;
    }
}

// ---------------------------------------------------------------------------
extern "C" void kernel_launch(void* const* d_in, const int* in_sizes, int n_in,
                              void* d_out, int out_size)
{
    const float* x   = (const float*)d_in[0];
    const unsigned char* xmask = (const unsigned char*)d_in[1];
    const int*   pos = (const int*)d_in[2];
    const float* pe  = (const float*)d_in[3];
    const float* wq  = (const float*)d_in[4];
    const float* bq  = (const float*)d_in[5];
    const float* wk  = (const float*)d_in[6];
    const float* bk  = (const float*)d_in[7];
    const float* wv  = (const float*)d_in[8];
    const float* bv  = (const float*)d_in[9];
    const float* lng = (const float*)d_in[10];
    const float* lnb = (const float*)d_in[11];
    const float* lsg = (const float*)d_in[12];
    float* out = (float*)d_out;

    conv_x_kernel<<<(MTOT * Dq / 4) / 256, 256>>>(x);
    conv_w_kernel<<<(Dq * Dq) / 256, 256>>>(wq, wk, wv);
    conv_m_kernel<<<(NHEADS * Tq) / 256, 256>>>(xmask);

    cudaFuncSetAttribute(qkv_mma_kernel,
                         cudaFuncAttributeMaxDynamicSharedMemorySize, QK_SMEM);
    qkv_mma_kernel<<<dim3(3, MTOT / 128), 256, QK_SMEM>>>(pos, pe, bq, bk, bv);

    transpose_v_kernel<<<dim3(Tq / 64, Dq / 64, NHEADS), 256>>>();

    cudaFuncSetAttribute(attn_fp8_kernel,
                         cudaFuncAttributeMaxDynamicSharedMemorySize, ATTN_SMEM);
    attn_fp8_kernel<<<dim3(Tq / 128, NHEADS), 256, ATTN_SMEM>>>(
        x, lng, lnb, lsg, out);
}

// round 9
// speedup vs baseline: 1.2062x; 1.2062x over previous
#include <cuda_runtime.h>
#include <cuda_fp16.h>
#include <math_constants.h>
#include <cstdint>

#define Bq 4
#define Tq 1024
#define Cq 16
#define Dq 256
#define NHEADS (Bq*Cq)
#define MTOT (Bq*Tq*Cq)

__device__ __align__(128) __half g_xb[(size_t)MTOT * Dq];
__device__ __align__(128) __half g_wb[3 * Dq * Dq];
__device__ __align__(128) __half g_q [(size_t)NHEADS * Tq * Dq];
__device__ __align__(128) __half g_k [(size_t)NHEADS * Tq * Dq];
__device__ __align__(128) __half g_v [(size_t)NHEADS * Tq * Dq];
__device__ __align__(128) unsigned char g_mt[NHEADS * Tq];

static __device__ __forceinline__ unsigned packh(float a, float b) {
    __half2 h = __floats2half2_rn(a, b);
    return *reinterpret_cast<unsigned*>(&h);
}
static __device__ __forceinline__ float2 unph(unsigned u) {
    __half2 h = *reinterpret_cast<__half2*>(&u);
    return __half22float2(h);
}
static __device__ __forceinline__ void mma_f16_f16(
    unsigned& d0, unsigned& d1,
    unsigned a0, unsigned a1, unsigned a2, unsigned a3,
    unsigned b0, unsigned b1)
{
    asm volatile(
        "mma.sync.aligned.m16n8k16.row.col.f16.f16.f16.f16 "
        "{%0,%1}, {%2,%3,%4,%5}, {%6,%7}, {%0,%1};\n"
        : "+r"(d0), "+r"(d1)
        : "r"(a0), "r"(a1), "r"(a2), "r"(a3), "r"(b0), "r"(b1));
}
static __device__ __forceinline__ void ldsm_x4(
    unsigned& r0, unsigned& r1, unsigned& r2, unsigned& r3, unsigned addr)
{
    asm volatile("ldmatrix.sync.aligned.m8n8.x4.shared.b16 {%0,%1,%2,%3}, [%4];"
        : "=r"(r0), "=r"(r1), "=r"(r2), "=r"(r3) : "r"(addr));
}
static __device__ __forceinline__ void ldsm_x4_t(
    unsigned& r0, unsigned& r1, unsigned& r2, unsigned& r3, unsigned addr)
{
    asm volatile("ldmatrix.sync.aligned.m8n8.x4.trans.shared.b16 {%0,%1,%2,%3}, [%4];"
        : "=r"(r0), "=r"(r1), "=r"(r2), "=r"(r3) : "r"(addr));
}

#define CPA16(d, s) asm volatile("cp.async.cg.shared.global [%0], [%1], 16;" :: "r"(d), "l"(s))
#define CP_COMMIT() asm volatile("cp.async.commit_group;")
#define CP_WAIT(n)  asm volatile("cp.async.wait_group %0;" :: "n"(n))

// ---------------------------------------------------------------------------
__global__ void conv_x_kernel(const float* __restrict__ x)
{
    int i = blockIdx.x * blockDim.x + threadIdx.x;
    const float4 v = ((const float4*)x)[i];
    ((uint2*)g_xb)[i] = make_uint2(packh(v.x, v.y), packh(v.z, v.w));
}
__global__ void conv_w_kernel(const float* __restrict__ wq,
                              const float* __restrict__ wk,
                              const float* __restrict__ wv)
{
    int i = blockIdx.x * blockDim.x + threadIdx.x;
    g_wb[i]          = __float2half(wq[i]);
    g_wb[i + 65536]  = __float2half(wk[i]);
    g_wb[i + 131072] = __float2half(wv[i]);
}
__global__ void conv_m_kernel(const unsigned char* __restrict__ xmask)
{
    int i = blockIdx.x * blockDim.x + threadIdx.x;
    int h = i >> 10, t = i & 1023;
    int b = h >> 4,  c = h & 15;
    g_mt[i] = xmask[(size_t)((b << 10) + t) * Cq + c];
}

// ---------------------------------------------------------------------------
// QKV projection (R6, unchanged): mma.sync f16/f16acc, CTA 128Mx256N.
// ---------------------------------------------------------------------------
#define QX_OFF 0u
#define QW0_OFF 67584u
#define QW1_OFF 137216u
#define QK_SMEM (137216 + 69632)

__global__ __launch_bounds__(256, 1) void qkv_mma_kernel(
    const int*   __restrict__ pos,
    const float* __restrict__ pe,
    const float* __restrict__ bq,
    const float* __restrict__ bk,
    const float* __restrict__ bv)
{
    extern __shared__ char sm[];
    const unsigned su = (unsigned)__cvta_generic_to_shared(sm);
    const int tid = threadIdx.x, w = tid >> 5, lane = tid & 31;
    const int q = lane & 3, lr = lane >> 2, g = lane >> 3, r8 = lane & 7;
    const int wm = w >> 2, wn = w & 3;
    const int mat = blockIdx.x;
    const int m0  = blockIdx.y * 128;

    const __half* xb = g_xb + (size_t)m0 * Dq;
#pragma unroll
    for (int it = 0; it < 16; ++it) {
        int idx = it * 256 + tid;
        int row = idx >> 5, ch = idx & 31;
        CPA16(su + QX_OFF + (unsigned)(row * 528 + ch * 16), xb + row * Dq + ch * 8);
    }
    const __half* wb = g_wb + mat * 65536;
#pragma unroll
    for (int it = 0; it < 16; ++it) {
        int idx = it * 256 + tid;
        int row = idx >> 4, ch = idx & 15;
        CPA16(su + QW0_OFF + (unsigned)(row * 272 + ch * 16), wb + row * Dq + ch * 8);
    }
    CP_COMMIT();
#pragma unroll
    for (int it = 0; it < 16; ++it) {
        int idx = it * 256 + tid;
        int row = idx >> 4, ch = idx & 15;
        CPA16(su + QW1_OFF + (unsigned)(row * 272 + ch * 16), wb + row * Dq + 128 + ch * 8);
    }
    CP_COMMIT();

    unsigned acc[4][8][2];
#pragma unroll
    for (int mt = 0; mt < 4; ++mt)
#pragma unroll
        for (int nt = 0; nt < 8; ++nt) { acc[mt][nt][0] = 0u; acc[mt][nt][1] = 0u; }

    const unsigned a_base = su + QX_OFF +
        (unsigned)((wm * 64 + (g & 1) * 8 + r8) * 528 + ((g >> 1) * 8) * 2);
    const unsigned b_base = su + QW0_OFF +
        (unsigned)((wn * 64 + (g >> 1) * 8 + r8) * 272 + ((g & 1) * 8) * 2);

#pragma unroll
    for (int ph = 0; ph < 2; ++ph) {
        if (ph == 0) { CP_WAIT(1); } else { CP_WAIT(0); }
        __syncthreads();
        const unsigned ab = a_base + (unsigned)ph * 256u;
        const unsigned bb = b_base + (unsigned)ph * (QW1_OFF - QW0_OFF);
#pragma unroll
        for (int kk = 0; kk < 8; ++kk) {
            unsigned af[4][4];
#pragma unroll
            for (int mt = 0; mt < 4; ++mt)
                ldsm_x4(af[mt][0], af[mt][1], af[mt][2], af[mt][3],
                        ab + (unsigned)(mt * 16 * 528) + kk * 32);
#pragma unroll
            for (int nt = 0; nt < 4; ++nt) {
                unsigned b0, b1, b2, b3;
                ldsm_x4(b0, b1, b2, b3, bb + (unsigned)(nt * 16 * 272) + kk * 32);
#pragma unroll
                for (int mt = 0; mt < 4; ++mt) {
                    mma_f16_f16(acc[mt][2*nt][0],   acc[mt][2*nt][1],
                                af[mt][0], af[mt][1], af[mt][2], af[mt][3], b0, b1);
                    mma_f16_f16(acc[mt][2*nt+1][0], acc[mt][2*nt+1][1],
                                af[mt][0], af[mt][1], af[mt][2], af[mt][3], b2, b3);
                }
            }
        }
    }

    const float* bias = (mat == 0) ? bq : (mat == 1) ? bk : bv;
    __half* outp = (mat == 0) ? g_q : (mat == 1) ? g_k : g_v;

#pragma unroll
    for (int mt = 0; mt < 4; ++mt) {
        const int tokA = m0 + wm * 64 + mt * 16 + lr;
        const int tokB = tokA + 8;
        const int bA = tokA >> 14, tA = (tokA >> 4) & (Tq-1), cA = tokA & (Cq-1);
        const int bB = tokB >> 14, tB = (tokB >> 4) & (Tq-1), cB = tokB & (Cq-1);
        __half* rowA = outp + ((size_t)(bA * Cq + cA) * Tq + tA) * Dq;
        __half* rowB = outp + ((size_t)(bB * Cq + cB) * Tq + tB) * Dq;
        int pA = 0, pB = 0;
        if (mat < 2) { pA = pos[tokA]; pB = pos[tokB]; }
#pragma unroll
        for (int nt = 0; nt < 8; ++nt) {
            const int col = wn * 64 + nt * 8 + 2 * q;
            const float2 b2 = *(const float2*)(bias + col);
            float2 va = unph(acc[mt][nt][0]);
            float2 vb = unph(acc[mt][nt][1]);
            float v0 = va.x + b2.x, v1 = va.y + b2.y;
            float v2 = vb.x + b2.x, v3 = vb.y + b2.y;
            if (mat < 2) {
                const float2 csA = *(const float2*)(pe + (size_t)pA * Dq + col);
                const float2 csB = *(const float2*)(pe + (size_t)pB * Dq + col);
                float r0 = v0 * csA.x - v1 * csA.y;
                v1 = v0 * csA.y + v1 * csA.x; v0 = r0;
                float r2 = v2 * csB.x - v3 * csB.y;
                v3 = v2 * csB.y + v3 * csB.x; v2 = r2;
            }
            *(unsigned*)&rowA[col] = packh(v0, v1);
            *(unsigned*)&rowB[col] = packh(v2, v3);
        }
    }
}

// ---------------------------------------------------------------------------
// Flash attention: R6 structure + frozen-max softmax + 3-stage cp.async ring.
// CTA = (head, 128 q-rows); 8 warps x 16 rows; K-tiles 64, 16 iters.
// ---------------------------------------------------------------------------
#define STR 264
#define KBYTES (64 * STR * 2)          // 33792
#define STAGEB (2 * KBYTES)            // 67584 (K tile + V tile)
#define QM_OFF (3 * STAGEB)            // 202752
#define KM_OFF (QM_OFF + 128)          // 202880 (3 x 64)
#define ATTN_SMEM (KM_OFF + 192 + 64)

__global__ __launch_bounds__(256, 1) void attn_fm_kernel(
    const float* __restrict__ x,
    const float* __restrict__ lng,
    const float* __restrict__ lnb,
    const float* __restrict__ lsg,
    float* __restrict__ out)
{
    extern __shared__ char smraw[];
    const unsigned char* sQm  = (const unsigned char*)(smraw + QM_OFF);
    const unsigned char* sKmB = (const unsigned char*)(smraw + KM_OFF);
    const unsigned su = (unsigned)__cvta_generic_to_shared(smraw);

    const int tid  = threadIdx.x;
    const int w    = tid >> 5;
    const int lane = tid & 31;
    const int q    = lane & 3;
    const int lr   = lane >> 2;
    const int g    = lane >> 3;
    const int r8   = lane & 7;

    const int h  = blockIdx.y;
    const int b  = h >> 4, c = h & 15;
    const int q0 = blockIdx.x * 128;

    const __half* qg = g_q + ((size_t)h * Tq + q0) * Dq;
    const __half* kg = g_k + (size_t)h * Tq * Dq;
    const __half* vg = g_v + (size_t)h * Tq * Dq;
    const unsigned char* mg = g_mt + h * Tq;

    // ---- stage Q into stage-0 region (freed before issue(0)) ----
#pragma unroll
    for (int it = 0; it < 16; ++it) {
        int idx = it * 256 + tid;
        int row = idx >> 5, cc = idx & 31;
        CPA16(su + (unsigned)(row * STR * 2 + cc * 16), qg + row * Dq + cc * 8);
    }
    if (tid < 8) CPA16(su + QM_OFF + tid * 16, mg + q0 + tid * 16);
    CP_COMMIT(); CP_WAIT(0);
    __syncthreads();

    unsigned qf[16][4];
    const unsigned qa = su +
        ((unsigned)(w * 16 + (g & 1) * 8 + r8) * STR + (g >> 1) * 8) * 2;
#pragma unroll
    for (int kk = 0; kk < 16; ++kk)
        ldsm_x4(qf[kk][0], qf[kk][1], qf[kk][2], qf[kk][3], qa + kk * 32);
    const int qmA = sQm[w * 16 + lr];
    const int qmB = sQm[w * 16 + lr + 8];
    __syncthreads();

    auto issue = [&](int kt) {
        const int st = kt % 3;
        const unsigned sb = su + st * STAGEB;
        const int k0 = kt * 64;
#pragma unroll
        for (int it = 0; it < 8; ++it) {
            int idx = it * 256 + tid;
            int row = idx >> 5, cc = idx & 31;
            CPA16(sb + (unsigned)(row * STR * 2 + cc * 16),
                  kg + (size_t)(k0 + row) * Dq + cc * 8);
            CPA16(sb + KBYTES + (unsigned)(row * STR * 2 + cc * 16),
                  vg + (size_t)(k0 + row) * Dq + cc * 8);
        }
        if (tid < 4) CPA16(su + KM_OFF + st * 64 + tid * 16, mg + k0 + tid * 16);
    };
    issue(0); CP_COMMIT();
    issue(1); CP_COMMIT();

    const unsigned koff = ((unsigned)((g >> 1) * 8 + r8) * STR + (g & 1) * 8) * 2;
    const unsigned voff = ((unsigned)((g & 1) * 8 + r8) * STR + (g >> 1) * 8) * 2;

    unsigned oacc[32][2];
#pragma unroll
    for (int j = 0; j < 32; ++j) { oacc[j][0] = 0u; oacc[j][1] = 0u; }
    float lsumA = 0.f, lsumB = 0.f, mUA = 0.f, mUB = 0.f;

    for (int kt = 0; kt < 16; ++kt) {
        CP_WAIT(1);
        __syncthreads();
        if (kt + 2 < 16) { issue(kt + 2); }
        CP_COMMIT();

        const int st = kt % 3;
        const unsigned kb_s = su + st * STAGEB;
        const unsigned vb_s = kb_s + KBYTES;
        const unsigned char* km = sKmB + st * 64;

        // ---- S = Q K^T (f16 accum) ----
        unsigned sacc[8][2];
#pragma unroll
        for (int nf = 0; nf < 8; ++nf) { sacc[nf][0] = 0u; sacc[nf][1] = 0u; }
#pragma unroll
        for (int kk = 0; kk < 16; ++kk) {
#pragma unroll
            for (int ng = 0; ng < 4; ++ng) {
                unsigned b0, b1, b2, b3;
                ldsm_x4(b0, b1, b2, b3,
                        kb_s + (unsigned)(ng * 16 * STR * 2) + kk * 32 + koff);
                mma_f16_f16(sacc[2*ng][0],   sacc[2*ng][1],
                            qf[kk][0], qf[kk][1], qf[kk][2], qf[kk][3], b0, b1);
                mma_f16_f16(sacc[2*ng+1][0], sacc[2*ng+1][1],
                            qf[kk][0], qf[kk][1], qf[kk][2], qf[kk][3], b2, b3);
            }
        }

        // ---- frozen max from tile 0 ----
        if (kt == 0) {
            float tA = -CUDART_INF_F, tB = -CUDART_INF_F;
#pragma unroll
            for (int nf = 0; nf < 8; ++nf) {
                const int cc = nf * 8 + 2 * q;
                const int k0m = km[cc], k1m = km[cc + 1];
                const float2 lo = unph(sacc[nf][0]);
                const float2 hi = unph(sacc[nf][1]);
                float s0 = (qmA | k0m) ? -CUDART_INF_F : lo.x * 0.0625f;
                float s1 = (qmA | k1m) ? -CUDART_INF_F : lo.y * 0.0625f;
                float s2 = (qmB | k0m) ? -CUDART_INF_F : hi.x * 0.0625f;
                float s3 = (qmB | k1m) ? -CUDART_INF_F : hi.y * 0.0625f;
                tA = fmaxf(tA, fmaxf(s0, s1));
                tB = fmaxf(tB, fmaxf(s2, s3));
            }
            tA = fmaxf(tA, __shfl_xor_sync(0xffffffffu, tA, 1));
            tA = fmaxf(tA, __shfl_xor_sync(0xffffffffu, tA, 2));
            tB = fmaxf(tB, __shfl_xor_sync(0xffffffffu, tB, 1));
            tB = fmaxf(tB, __shfl_xor_sync(0xffffffffu, tB, 2));
            mUA = (tA < -1e30f) ? 0.f : tA;
            mUB = (tB < -1e30f) ? 0.f : tB;
        }

        // ---- p = exp(s*scale - mU) (masked -> 0), clamp, pack f16 ----
        unsigned pa[4][4];
#pragma unroll
        for (int kk = 0; kk < 4; ++kk) {
            const int nfA = 2 * kk, nfB = 2 * kk + 1;
            const int c0 = nfA * 8 + 2 * q, c1 = nfB * 8 + 2 * q;
            const int ka0 = km[c0], ka1 = km[c0 + 1];
            const int kb0 = km[c1], kb1 = km[c1 + 1];
            const float2 lA = unph(sacc[nfA][0]);
            const float2 hA = unph(sacc[nfA][1]);
            const float2 lB = unph(sacc[nfB][0]);
            const float2 hB = unph(sacc[nfB][1]);
            float p00 = (qmA | ka0) ? 0.f : fminf(__expf(lA.x * 0.0625f - mUA), 60000.f);
            float p01 = (qmA | ka1) ? 0.f : fminf(__expf(lA.y * 0.0625f - mUA), 60000.f);
            float p02 = (qmB | ka0) ? 0.f : fminf(__expf(hA.x * 0.0625f - mUB), 60000.f);
            float p03 = (qmB | ka1) ? 0.f : fminf(__expf(hA.y * 0.0625f - mUB), 60000.f);
            float p10 = (qmA | kb0) ? 0.f : fminf(__expf(lB.x * 0.0625f - mUA), 60000.f);
            float p11 = (qmA | kb1) ? 0.f : fminf(__expf(lB.y * 0.0625f - mUA), 60000.f);
            float p12 = (qmB | kb0) ? 0.f : fminf(__expf(hB.x * 0.0625f - mUB), 60000.f);
            float p13 = (qmB | kb1) ? 0.f : fminf(__expf(hB.y * 0.0625f - mUB), 60000.f);
            lsumA += p00 + p01 + p10 + p11;
            lsumB += p02 + p03 + p12 + p13;
            pa[kk][0] = packh(p00, p01);
            pa[kk][1] = packh(p02, p03);
            pa[kk][2] = packh(p10, p11);
            pa[kk][3] = packh(p12, p13);
        }

        // ---- O += P V (no rescale; frozen max) ----
#pragma unroll
        for (int kk = 0; kk < 4; ++kk) {
#pragma unroll
            for (int dg = 0; dg < 16; ++dg) {
                unsigned v0, v1, v2, v3;
                ldsm_x4_t(v0, v1, v2, v3,
                          vb_s + (unsigned)(kk * 16 * STR * 2) + dg * 32 + voff);
                mma_f16_f16(oacc[2*dg][0],   oacc[2*dg][1],
                            pa[kk][0], pa[kk][1], pa[kk][2], pa[kk][3], v0, v1);
                mma_f16_f16(oacc[2*dg+1][0], oacc[2*dg+1][1],
                            pa[kk][0], pa[kk][1], pa[kk][2], pa[kk][3], v2, v3);
            }
        }
    }

    // ---- epilogue: residual + LayerScale + LayerNorm ----
    lsumA += __shfl_xor_sync(0xffffffffu, lsumA, 1);
    lsumA += __shfl_xor_sync(0xffffffffu, lsumA, 2);
    lsumB += __shfl_xor_sync(0xffffffffu, lsumB, 1);
    lsumB += __shfl_xor_sync(0xffffffffu, lsumB, 2);
    const float invA = (lsumA > 0.f) ? (1.f / lsumA) : 0.f;
    const float invB = (lsumB > 0.f) ? (1.f / lsumB) : 0.f;

    const int gtA = q0 + w * 16 + lr;
    const int gtB = gtA + 8;
    const size_t miA = (size_t)(b * Tq + gtA) * Cq + c;
    const size_t miB = (size_t)(b * Tq + gtB) * Cq + c;
    const float* xA = x + miA * Dq;
    const float* xB = x + miB * Dq;

    float yv[32][4];
    float sumA = 0.f, ssqA = 0.f, sumB = 0.f, ssqB = 0.f;
#pragma unroll
    for (int j = 0; j < 32; ++j) {
        const int cc = j * 8 + 2 * q;
        const float2 g2 = *(const float2*)(lsg + cc);
        const float2 xa = *(const float2*)(xA + cc);
        const float2 xb2 = *(const float2*)(xB + cc);
        const float2 oa = unph(oacc[j][0]);
        const float2 ob = unph(oacc[j][1]);
        float y0 = xa.x  + g2.x * (oa.x * invA);
        float y1 = xa.y  + g2.y * (oa.y * invA);
        float y2 = xb2.x + g2.x * (ob.x * invB);
        float y3 = xb2.y + g2.y * (ob.y * invB);
        yv[j][0] = y0; yv[j][1] = y1; yv[j][2] = y2; yv[j][3] = y3;
        sumA += y0 + y1;  ssqA += y0 * y0 + y1 * y1;
        sumB += y2 + y3;  ssqB += y2 * y2 + y3 * y3;
    }
    sumA += __shfl_xor_sync(0xffffffffu, sumA, 1);
    sumA += __shfl_xor_sync(0xffffffffu, sumA, 2);
    ssqA += __shfl_xor_sync(0xffffffffu, ssqA, 1);
    ssqA += __shfl_xor_sync(0xffffffffu, ssqA, 2);
    sumB += __shfl_xor_sync(0xffffffffu, sumB, 1);
    sumB += __shfl_xor_sync(0xffffffffu, sumB, 2);
    ssqB += __shfl_xor_sync(0xffffffffu, ssqB, 1);
    ssqB += __shfl_xor_sync(0xffffffffu, ssqB, 2);

    const float muA = sumA * (1.f / 256.f);
    const float muB = sumB * (1.f / 256.f);
    const float rsA = rsqrtf(ssqA * (1.f / 256.f) - muA * muA + 1e-5f);
    const float rsB = rsqrtf(ssqB * (1.f / 256.f) - muB * muB + 1e-5f);

    float* oA = out + miA * Dq;
    float* oB = out + miB * Dq;
#pragma unroll
    for (int j = 0; j < 32; ++j) {
        const int cc = j * 8 + 2 * q;
        const float2 gg = *(const float2*)(lng + cc);
        const float2 bb = *(const float2*)(lnb + cc);
        float2 r0, r1;
        r0.x = (yv[j][0] - muA) * rsA * gg.x + bb.x;
        r0.y = (yv[j][1] - muA) * rsA * gg.y + bb.y;
        r1.x = (yv[j][2] - muB) * rsB * gg.x + bb.x;
        r1.y = (yv[j][3] - muB) * rsB * gg.y + bb.y;
        *(float2*)(oA + cc) = r0;
        *(float2*)(oB + cc) = r1;
    }
}

// ---------------------------------------------------------------------------
extern "C" void kernel_launch(void* const* d_in, const int* in_sizes, int n_in,
                              void* d_out, int out_size)
{
    const float* x   = (const float*)d_in[0];
    const unsigned char* xmask = (const unsigned char*)d_in[1];
    const int*   pos = (const int*)d_in[2];
    const float* pe  = (const float*)d_in[3];
    const float* wq  = (const float*)d_in[4];
    const float* bq  = (const float*)d_in[5];
    const float* wk  = (const float*)d_in[6];
    const float* bk  = (const float*)d_in[7];
    const float* wv  = (const float*)d_in[8];
    const float* bv  = (const float*)d_in[9];
    const float* lng = (const float*)d_in[10];
    const float* lnb = (const float*)d_in[11];
    const float* lsg = (const float*)d_in[12];
    float* out = (float*)d_out;

    conv_x_kernel<<<(MTOT * Dq / 4) / 256, 256>>>(x);
    conv_w_kernel<<<(Dq * Dq) / 256, 256>>>(wq, wk, wv);
    conv_m_kernel<<<(NHEADS * Tq) / 256, 256>>>(xmask);

    cudaFuncSetAttribute(qkv_mma_kernel,
                         cudaFuncAttributeMaxDynamicSharedMemorySize, QK_SMEM);
    qkv_mma_kernel<<<dim3(3, MTOT / 128), 256, QK_SMEM>>>(pos, pe, bq, bk, bv);

    cudaFuncSetAttribute(attn_fm_kernel,
                         cudaFuncAttributeMaxDynamicSharedMemorySize, ATTN_SMEM);
    attn_fm_kernel<<<dim3(Tq / 128, NHEADS), 256, ATTN_SMEM>>>(
        x, lng, lnb, lsg, out);
}

// round 11
// speedup vs baseline: 1.2475x; 1.0342x over previous
#include <cuda_runtime.h>
#include <cuda_fp16.h>
#include <math_constants.h>
#include <cstdint>

#define Bq 4
#define Tq 1024
#define Cq 16
#define Dq 256
#define NHEADS (Bq*Cq)
#define MTOT (Bq*Tq*Cq)

__device__ __align__(128) __half g_xb[(size_t)MTOT * Dq];
__device__ __align__(128) __half g_wb[3 * Dq * Dq];
__device__ __align__(128) __half g_q [(size_t)NHEADS * Tq * Dq];
__device__ __align__(128) __half g_k [(size_t)NHEADS * Tq * Dq];
__device__ __align__(128) __half g_v [(size_t)NHEADS * Tq * Dq];
__device__ __align__(128) unsigned char g_mt[NHEADS * Tq];

static __device__ __forceinline__ unsigned packh(float a, float b) {
    __half2 h = __floats2half2_rn(a, b);
    return *reinterpret_cast<unsigned*>(&h);
}
static __device__ __forceinline__ float2 unph(unsigned u) {
    __half2 h = *reinterpret_cast<__half2*>(&u);
    return __half22float2(h);
}
static __device__ __forceinline__ unsigned hmul2u(unsigned a, unsigned b) {
    __half2 r = __hmul2(*reinterpret_cast<__half2*>(&a),
                        *reinterpret_cast<__half2*>(&b));
    return *reinterpret_cast<unsigned*>(&r);
}
static __device__ __forceinline__ void mma_f16_f16(
    unsigned& d0, unsigned& d1,
    unsigned a0, unsigned a1, unsigned a2, unsigned a3,
    unsigned b0, unsigned b1)
{
    asm volatile(
        "mma.sync.aligned.m16n8k16.row.col.f16.f16.f16.f16 "
        "{%0,%1}, {%2,%3,%4,%5}, {%6,%7}, {%0,%1};\n"
        : "+r"(d0), "+r"(d1)
        : "r"(a0), "r"(a1), "r"(a2), "r"(a3), "r"(b0), "r"(b1));
}
static __device__ __forceinline__ void ldsm_x4(
    unsigned& r0, unsigned& r1, unsigned& r2, unsigned& r3, unsigned addr)
{
    asm volatile("ldmatrix.sync.aligned.m8n8.x4.shared.b16 {%0,%1,%2,%3}, [%4];"
        : "=r"(r0), "=r"(r1), "=r"(r2), "=r"(r3) : "r"(addr));
}
static __device__ __forceinline__ void ldsm_x4_t(
    unsigned& r0, unsigned& r1, unsigned& r2, unsigned& r3, unsigned addr)
{
    asm volatile("ldmatrix.sync.aligned.m8n8.x4.trans.shared.b16 {%0,%1,%2,%3}, [%4];"
        : "=r"(r0), "=r"(r1), "=r"(r2), "=r"(r3) : "r"(addr));
}

#define CPA16(d, s) asm volatile("cp.async.cg.shared.global [%0], [%1], 16;" :: "r"(d), "l"(s))
#define CP_COMMIT() asm volatile("cp.async.commit_group;")
#define CP_WAIT(n)  asm volatile("cp.async.wait_group %0;" :: "n"(n))

// ---------------------------------------------------------------------------
__global__ void conv_x_kernel(const float* __restrict__ x)
{
    int i = blockIdx.x * blockDim.x + threadIdx.x;
    const float4 v = ((const float4*)x)[i];
    ((uint2*)g_xb)[i] = make_uint2(packh(v.x, v.y), packh(v.z, v.w));
}
__global__ void conv_w_kernel(const float* __restrict__ wq,
                              const float* __restrict__ wk,
                              const float* __restrict__ wv)
{
    int i = blockIdx.x * blockDim.x + threadIdx.x;
    g_wb[i]          = __float2half(wq[i]);
    g_wb[i + 65536]  = __float2half(wk[i]);
    g_wb[i + 131072] = __float2half(wv[i]);
}
__global__ void conv_m_kernel(const unsigned char* __restrict__ xmask)
{
    int i = blockIdx.x * blockDim.x + threadIdx.x;
    int h = i >> 10, t = i & 1023;
    int b = h >> 4,  c = h & 15;
    g_mt[i] = xmask[(size_t)((b << 10) + t) * Cq + c];
}

// ---------------------------------------------------------------------------
// Persistent-W QKV: grid (3, 148). CTA keeps its 256x256 weight matrix in
// smem; streams X in double-buffered 128x128 chunks (row stride 272 B).
// smem: XB0 @0 (34816), XB1 @34816, W0 @69632 (69632), W1 @139264 (69632).
// ---------------------------------------------------------------------------
#define XB_SZ 34816u
#define PW0_OFF 69632u
#define PW1_OFF 139264u
#define QK_SMEM (139264 + 69632)

__global__ __launch_bounds__(256, 1) void qkv_pers_kernel(
    const int*   __restrict__ pos,
    const float* __restrict__ pe,
    const float* __restrict__ bq,
    const float* __restrict__ bk,
    const float* __restrict__ bv)
{
    extern __shared__ char sm[];
    const unsigned su = (unsigned)__cvta_generic_to_shared(sm);
    const int tid = threadIdx.x, w = tid >> 5, lane = tid & 31;
    const int q = lane & 3, lr = lane >> 2, g = lane >> 3, r8 = lane & 7;
    const int wm = w >> 2, wn = w & 3;
    const int mat = blockIdx.x;
    const int by  = blockIdx.y;       // 0..147

    int nt = 0;
    for (int my = by; my < 512; my += 148) ++nt;
    const int nchunks = 2 * nt;

    // ---- load W (both halves, one commit group), 272-B row stride ----
    const __half* wb = g_wb + mat * 65536;
#pragma unroll
    for (int it = 0; it < 16; ++it) {
        int idx = it * 256 + tid;
        int row = idx >> 4, ch = idx & 15;
        CPA16(su + PW0_OFF + (unsigned)(row * 272 + ch * 16), wb + row * Dq + ch * 8);
        CPA16(su + PW1_OFF + (unsigned)(row * 272 + ch * 16), wb + row * Dq + 128 + ch * 8);
    }
    CP_COMMIT();

    auto issue_x = [&](int ci) {
        const int m0 = (by + (ci >> 1) * 148) << 7;
        const int khalf = ci & 1;
        const unsigned xb_s = su + (unsigned)(ci & 1) * XB_SZ;
        const __half* src = g_xb + (size_t)m0 * Dq + khalf * 128;
#pragma unroll
        for (int it = 0; it < 8; ++it) {
            int idx = it * 256 + tid;
            int row = idx >> 4, ch = idx & 15;
            CPA16(xb_s + (unsigned)(row * 272 + ch * 16), src + row * Dq + ch * 8);
        }
    };
    issue_x(0); CP_COMMIT();
    if (nchunks > 1) { issue_x(1); } CP_COMMIT();

    const float* bias = (mat == 0) ? bq : (mat == 1) ? bk : bv;
    __half* outp = (mat == 0) ? g_q : (mat == 1) ? g_k : g_v;

    const unsigned a_lane = (unsigned)((wm * 64 + (g & 1) * 8 + r8) * 272
                                       + ((g >> 1) * 8) * 2);
    const unsigned b_lane = (unsigned)((wn * 64 + (g >> 1) * 8 + r8) * 272
                                       + ((g & 1) * 8) * 2);

    unsigned acc[4][8][2];

    for (int ci = 0; ci < nchunks; ++ci) {
        CP_WAIT(1);
        __syncthreads();
        const int phase = ci & 1;
        if (phase == 0) {
#pragma unroll
            for (int mt = 0; mt < 4; ++mt)
#pragma unroll
                for (int nt2 = 0; nt2 < 8; ++nt2) { acc[mt][nt2][0] = 0u; acc[mt][nt2][1] = 0u; }
        }
        const unsigned ab = su + (unsigned)(ci & 1) * XB_SZ + a_lane;
        const unsigned bb = su + (phase ? PW1_OFF : PW0_OFF) + b_lane;
#pragma unroll
        for (int kk = 0; kk < 8; ++kk) {
            unsigned af[4][4];
#pragma unroll
            for (int mt = 0; mt < 4; ++mt)
                ldsm_x4(af[mt][0], af[mt][1], af[mt][2], af[mt][3],
                        ab + (unsigned)(mt * 16 * 272) + kk * 32);
#pragma unroll
            for (int nt2 = 0; nt2 < 4; ++nt2) {
                unsigned b0, b1, b2, b3;
                ldsm_x4(b0, b1, b2, b3, bb + (unsigned)(nt2 * 16 * 272) + kk * 32);
#pragma unroll
                for (int mt = 0; mt < 4; ++mt) {
                    mma_f16_f16(acc[mt][2*nt2][0],   acc[mt][2*nt2][1],
                                af[mt][0], af[mt][1], af[mt][2], af[mt][3], b0, b1);
                    mma_f16_f16(acc[mt][2*nt2+1][0], acc[mt][2*nt2+1][1],
                                af[mt][0], af[mt][1], af[mt][2], af[mt][3], b2, b3);
                }
            }
        }
        __syncthreads();
        if (ci + 2 < nchunks) { issue_x(ci + 2); }
        CP_COMMIT();

        if (phase == 1) {
            const int m0 = (by + (ci >> 1) * 148) << 7;
#pragma unroll
            for (int mt = 0; mt < 4; ++mt) {
                const int tokA = m0 + wm * 64 + mt * 16 + lr;
                const int tokB = tokA + 8;
                const int bA = tokA >> 14, tA = (tokA >> 4) & (Tq-1), cA = tokA & (Cq-1);
                const int bB = tokB >> 14, tB = (tokB >> 4) & (Tq-1), cB = tokB & (Cq-1);
                __half* rowA = outp + ((size_t)(bA * Cq + cA) * Tq + tA) * Dq;
                __half* rowB = outp + ((size_t)(bB * Cq + cB) * Tq + tB) * Dq;
                int pA = 0, pB = 0;
                if (mat < 2) { pA = pos[tokA]; pB = pos[tokB]; }
#pragma unroll
                for (int nt2 = 0; nt2 < 8; ++nt2) {
                    const int col = wn * 64 + nt2 * 8 + 2 * q;
                    const float2 b2 = *(const float2*)(bias + col);
                    float2 va = unph(acc[mt][nt2][0]);
                    float2 vb = unph(acc[mt][nt2][1]);
                    float v0 = va.x + b2.x, v1 = va.y + b2.y;
                    float v2 = vb.x + b2.x, v3 = vb.y + b2.y;
                    if (mat < 2) {
                        const float2 csA = *(const float2*)(pe + (size_t)pA * Dq + col);
                        const float2 csB = *(const float2*)(pe + (size_t)pB * Dq + col);
                        float r0 = v0 * csA.x - v1 * csA.y;
                        v1 = v0 * csA.y + v1 * csA.x; v0 = r0;
                        float r2 = v2 * csB.x - v3 * csB.y;
                        v3 = v2 * csB.y + v3 * csB.x; v2 = r2;
                    }
                    *(unsigned*)&rowA[col] = packh(v0, v1);
                    *(unsigned*)&rowB[col] = packh(v2, v3);
                }
            }
        }
    }
}

// ---------------------------------------------------------------------------
// Flash attention (exact R6 best-known): f16 HMMA f16-acc, Q frags in regs,
// online softmax, 2-stage cp.async, fused residual + LayerScale + LayerNorm.
// ---------------------------------------------------------------------------
#define STR 264
#define KBYTES (64 * STR * 2)
#define STAGEB (2 * KBYTES)

__global__ __launch_bounds__(256, 1) void attn_tc_kernel(
    const float* __restrict__ x,
    const float* __restrict__ lng,
    const float* __restrict__ lnb,
    const float* __restrict__ lsg,
    float* __restrict__ out)
{
    extern __shared__ char smraw[];
    unsigned char* sQm = (unsigned char*)(smraw + 2 * STAGEB);
    unsigned char* sKm = sQm + 128;
    const unsigned smem_u = (unsigned)__cvta_generic_to_shared(smraw);
    const unsigned sqm_u  = smem_u + 2 * STAGEB;
    const unsigned skm_u  = sqm_u + 128;

    const int tid  = threadIdx.x;
    const int w    = tid >> 5;
    const int lane = tid & 31;
    const int q    = lane & 3;
    const int lr   = lane >> 2;
    const int g    = lane >> 3;
    const int r8   = lane & 7;

    const int h  = blockIdx.y;
    const int b  = h >> 4, c = h & 15;
    const int q0 = blockIdx.x * 128;

    const __half* qg = g_q + ((size_t)h * Tq + q0) * Dq;
    const __half* kg = g_k + (size_t)h * Tq * Dq;
    const __half* vg = g_v + (size_t)h * Tq * Dq;
    const unsigned char* mg = g_mt + h * Tq;

    const unsigned qs = smem_u + STAGEB;
#pragma unroll
    for (int it = 0; it < 16; ++it) {
        int idx = it * 256 + tid;
        int row = idx >> 5, cc = idx & 31;
        CPA16(qs + (unsigned)(row * STR * 2 + cc * 16), qg + row * Dq + cc * 8);
    }
    if (tid < 8) CPA16(sqm_u + tid * 16, mg + q0 + tid * 16);
    CP_COMMIT();
    CP_WAIT(0);
    __syncthreads();

    unsigned qf[16][4];
    const unsigned qa_off = qs +
        ((unsigned)(w * 16 + (g & 1) * 8 + r8) * STR + (g >> 1) * 8) * 2;
#pragma unroll
    for (int kk = 0; kk < 16; ++kk)
        ldsm_x4(qf[kk][0], qf[kk][1], qf[kk][2], qf[kk][3], qa_off + kk * 32);
    const int qmA = sQm[w * 16 + lr];
    const int qmB = sQm[w * 16 + lr + 8];
    __syncthreads();

    auto issue = [&](int kt) {
        const int stage = kt & 1;
        const unsigned sb = smem_u + stage * STAGEB;
        const int k0 = kt * 64;
#pragma unroll
        for (int it = 0; it < 8; ++it) {
            int idx = it * 256 + tid;
            int row = idx >> 5, cc = idx & 31;
            CPA16(sb + (unsigned)(row * STR * 2 + cc * 16),
                  kg + (size_t)(k0 + row) * Dq + cc * 8);
            CPA16(sb + KBYTES + (unsigned)(row * STR * 2 + cc * 16),
                  vg + (size_t)(k0 + row) * Dq + cc * 8);
        }
        if (tid < 4) CPA16(skm_u + stage * 64 + tid * 16, mg + k0 + tid * 16);
    };
    issue(0); CP_COMMIT();
    issue(1); CP_COMMIT();

    const unsigned koff = ((unsigned)((g >> 1) * 8 + r8) * STR + (g & 1) * 8) * 2;
    const unsigned voff = ((unsigned)((g & 1) * 8 + r8) * STR + (g >> 1) * 8) * 2;

    unsigned oacc[32][2];
#pragma unroll
    for (int j = 0; j < 32; ++j) { oacc[j][0] = 0u; oacc[j][1] = 0u; }
    float mrunA = -CUDART_INF_F, mrunB = -CUDART_INF_F;
    float lsumA = 0.f, lsumB = 0.f;

    for (int kt = 0; kt < 16; ++kt) {
        CP_WAIT(1);
        __syncthreads();
        const int stage = kt & 1;
        const unsigned kb_s = smem_u + stage * STAGEB;
        const unsigned vb_s = kb_s + KBYTES;
        const unsigned char* km = sKm + stage * 64;

        unsigned sacc[8][2];
#pragma unroll
        for (int nf = 0; nf < 8; ++nf) { sacc[nf][0] = 0u; sacc[nf][1] = 0u; }
#pragma unroll
        for (int kk = 0; kk < 16; ++kk) {
#pragma unroll
            for (int ng = 0; ng < 4; ++ng) {
                unsigned b0, b1, b2, b3;
                ldsm_x4(b0, b1, b2, b3,
                        kb_s + (unsigned)(ng * 16 * STR * 2) + kk * 32 + koff);
                mma_f16_f16(sacc[2*ng][0],   sacc[2*ng][1],
                            qf[kk][0], qf[kk][1], qf[kk][2], qf[kk][3], b0, b1);
                mma_f16_f16(sacc[2*ng+1][0], sacc[2*ng+1][1],
                            qf[kk][0], qf[kk][1], qf[kk][2], qf[kk][3], b2, b3);
            }
        }

        float sv[8][4];
        float tmaxA = -CUDART_INF_F, tmaxB = -CUDART_INF_F;
#pragma unroll
        for (int nf = 0; nf < 8; ++nf) {
            const float2 lo = unph(sacc[nf][0]);
            const float2 hi = unph(sacc[nf][1]);
            const int cc = nf * 8 + 2 * q;
            const int k0m = km[cc], k1m = km[cc + 1];
            sv[nf][0] = (qmA | k0m) ? -CUDART_INF_F : lo.x * 0.0625f;
            sv[nf][1] = (qmA | k1m) ? -CUDART_INF_F : lo.y * 0.0625f;
            sv[nf][2] = (qmB | k0m) ? -CUDART_INF_F : hi.x * 0.0625f;
            sv[nf][3] = (qmB | k1m) ? -CUDART_INF_F : hi.y * 0.0625f;
            tmaxA = fmaxf(tmaxA, fmaxf(sv[nf][0], sv[nf][1]));
            tmaxB = fmaxf(tmaxB, fmaxf(sv[nf][2], sv[nf][3]));
        }
        tmaxA = fmaxf(tmaxA, __shfl_xor_sync(0xffffffffu, tmaxA, 1));
        tmaxA = fmaxf(tmaxA, __shfl_xor_sync(0xffffffffu, tmaxA, 2));
        tmaxB = fmaxf(tmaxB, __shfl_xor_sync(0xffffffffu, tmaxB, 1));
        tmaxB = fmaxf(tmaxB, __shfl_xor_sync(0xffffffffu, tmaxB, 2));

        const float mnA = fmaxf(mrunA, tmaxA);
        const float mnB = fmaxf(mrunB, tmaxB);
        const float corrA = (mnA == -CUDART_INF_F) ? 1.f : __expf(mrunA - mnA);
        const float corrB = (mnB == -CUDART_INF_F) ? 1.f : __expf(mrunB - mnB);
        const float mUA = (mnA == -CUDART_INF_F) ? 0.f : mnA;
        const float mUB = (mnB == -CUDART_INF_F) ? 0.f : mnB;
        lsumA *= corrA; lsumB *= corrB;
        mrunA = mnA; mrunB = mnB;

        unsigned pa[4][4];
#pragma unroll
        for (int kk = 0; kk < 4; ++kk) {
            float p00 = __expf(sv[2*kk][0]   - mUA);
            float p01 = __expf(sv[2*kk][1]   - mUA);
            float p02 = __expf(sv[2*kk][2]   - mUB);
            float p03 = __expf(sv[2*kk][3]   - mUB);
            float p10 = __expf(sv[2*kk+1][0] - mUA);
            float p11 = __expf(sv[2*kk+1][1] - mUA);
            float p12 = __expf(sv[2*kk+1][2] - mUB);
            float p13 = __expf(sv[2*kk+1][3] - mUB);
            lsumA += p00 + p01 + p10 + p11;
            lsumB += p02 + p03 + p12 + p13;
            pa[kk][0] = packh(p00, p01);
            pa[kk][1] = packh(p02, p03);
            pa[kk][2] = packh(p10, p11);
            pa[kk][3] = packh(p12, p13);
        }

        const unsigned cA2 = packh(corrA, corrA);
        const unsigned cB2 = packh(corrB, corrB);
#pragma unroll
        for (int j = 0; j < 32; ++j) {
            oacc[j][0] = hmul2u(oacc[j][0], cA2);
            oacc[j][1] = hmul2u(oacc[j][1], cB2);
        }

#pragma unroll
        for (int kk = 0; kk < 4; ++kk) {
#pragma unroll
            for (int dg = 0; dg < 16; ++dg) {
                unsigned v0, v1, v2, v3;
                ldsm_x4_t(v0, v1, v2, v3,
                          vb_s + (unsigned)(kk * 16 * STR * 2) + dg * 32 + voff);
                mma_f16_f16(oacc[2*dg][0],   oacc[2*dg][1],
                            pa[kk][0], pa[kk][1], pa[kk][2], pa[kk][3], v0, v1);
                mma_f16_f16(oacc[2*dg+1][0], oacc[2*dg+1][1],
                            pa[kk][0], pa[kk][1], pa[kk][2], pa[kk][3], v2, v3);
            }
        }
        __syncthreads();
        if (kt + 2 < 16) issue(kt + 2);
        CP_COMMIT();
    }

    lsumA += __shfl_xor_sync(0xffffffffu, lsumA, 1);
    lsumA += __shfl_xor_sync(0xffffffffu, lsumA, 2);
    lsumB += __shfl_xor_sync(0xffffffffu, lsumB, 1);
    lsumB += __shfl_xor_sync(0xffffffffu, lsumB, 2);
    const float invA = (lsumA > 0.f) ? (1.f / lsumA) : 0.f;
    const float invB = (lsumB > 0.f) ? (1.f / lsumB) : 0.f;

    const int gtA = q0 + w * 16 + lr;
    const int gtB = gtA + 8;
    const size_t miA = (size_t)(b * Tq + gtA) * Cq + c;
    const size_t miB = (size_t)(b * Tq + gtB) * Cq + c;
    const float* xA = x + miA * Dq;
    const float* xB = x + miB * Dq;

    float yv[32][4];
    float sumA = 0.f, ssqA = 0.f, sumB = 0.f, ssqB = 0.f;
#pragma unroll
    for (int j = 0; j < 32; ++j) {
        const int cc = j * 8 + 2 * q;
        const float2 g2 = *(const float2*)(lsg + cc);
        const float2 xa = *(const float2*)(xA + cc);
        const float2 xb2 = *(const float2*)(xB + cc);
        const float2 oa = unph(oacc[j][0]);
        const float2 ob = unph(oacc[j][1]);
        float y0 = xa.x  + g2.x * (oa.x * invA);
        float y1 = xa.y  + g2.y * (oa.y * invA);
        float y2 = xb2.x + g2.x * (ob.x * invB);
        float y3 = xb2.y + g2.y * (ob.y * invB);
        yv[j][0] = y0; yv[j][1] = y1; yv[j][2] = y2; yv[j][3] = y3;
        sumA += y0 + y1;  ssqA += y0 * y0 + y1 * y1;
        sumB += y2 + y3;  ssqB += y2 * y2 + y3 * y3;
    }
    sumA += __shfl_xor_sync(0xffffffffu, sumA, 1);
    sumA += __shfl_xor_sync(0xffffffffu, sumA, 2);
    ssqA += __shfl_xor_sync(0xffffffffu, ssqA, 1);
    ssqA += __shfl_xor_sync(0xffffffffu, ssqA, 2);
    sumB += __shfl_xor_sync(0xffffffffu, sumB, 1);
    sumB += __shfl_xor_sync(0xffffffffu, sumB, 2);
    ssqB += __shfl_xor_sync(0xffffffffu, ssqB, 1);
    ssqB += __shfl_xor_sync(0xffffffffu, ssqB, 2);

    const float muA = sumA * (1.f / 256.f);
    const float muB = sumB * (1.f / 256.f);
    const float rsA = rsqrtf(ssqA * (1.f / 256.f) - muA * muA + 1e-5f);
    const float rsB = rsqrtf(ssqB * (1.f / 256.f) - muB * muB + 1e-5f);

    float* oA = out + miA * Dq;
    float* oB = out + miB * Dq;
#pragma unroll
    for (int j = 0; j < 32; ++j) {
        const int cc = j * 8 + 2 * q;
        const float2 gg = *(const float2*)(lng + cc);
        const float2 bb = *(const float2*)(lnb + cc);
        float2 r0, r1;
        r0.x = (yv[j][0] - muA) * rsA * gg.x + bb.x;
        r0.y = (yv[j][1] - muA) * rsA * gg.y + bb.y;
        r1.x = (yv[j][2] - muB) * rsB * gg.x + bb.x;
        r1.y = (yv[j][3] - muB) * rsB * gg.y + bb.y;
        *(float2*)(oA + cc) = r0;
        *(float2*)(oB + cc) = r1;
    }
}

// ---------------------------------------------------------------------------
extern "C" void kernel_launch(void* const* d_in, const int* in_sizes, int n_in,
                              void* d_out, int out_size)
{
    const float* x   = (const float*)d_in[0];
    const unsigned char* xmask = (const unsigned char*)d_in[1];
    const int*   pos = (const int*)d_in[2];
    const float* pe  = (const float*)d_in[3];
    const float* wq  = (const float*)d_in[4];
    const float* bq  = (const float*)d_in[5];
    const float* wk  = (const float*)d_in[6];
    const float* bk  = (const float*)d_in[7];
    const float* wv  = (const float*)d_in[8];
    const float* bv  = (const float*)d_in[9];
    const float* lng = (const float*)d_in[10];
    const float* lnb = (const float*)d_in[11];
    const float* lsg = (const float*)d_in[12];
    float* out = (float*)d_out;

    conv_x_kernel<<<(MTOT * Dq / 4) / 256, 256>>>(x);
    conv_w_kernel<<<(Dq * Dq) / 256, 256>>>(wq, wk, wv);
    conv_m_kernel<<<(NHEADS * Tq) / 256, 256>>>(xmask);

    cudaFuncSetAttribute(qkv_pers_kernel,
                         cudaFuncAttributeMaxDynamicSharedMemorySize, QK_SMEM);
    qkv_pers_kernel<<<dim3(3, 148), 256, QK_SMEM>>>(pos, pe, bq, bk, bv);

    const int smem2 = 2 * STAGEB + 256;
    cudaFuncSetAttribute(attn_tc_kernel,
                         cudaFuncAttributeMaxDynamicSharedMemorySize, smem2);
    attn_tc_kernel<<<dim3(Tq / 128, NHEADS), 256, smem2>>>(
        x, lng, lnb, lsg, out);
}

// round 12
// speedup vs baseline: 1.2747x; 1.0219x over previous
#include <cuda_runtime.h>
#include <cuda_fp16.h>
#include <math_constants.h>
#include <cstdint>

#define Bq 4
#define Tq 1024
#define Cq 16
#define Dq 256
#define NHEADS (Bq*Cq)
#define MTOT (Bq*Tq*Cq)

__device__ __align__(128) __half g_xb[(size_t)MTOT * Dq];
__device__ __align__(128) __half g_wb[3 * Dq * Dq];
__device__ __align__(128) __half g_q [(size_t)NHEADS * Tq * Dq];
__device__ __align__(128) __half g_k [(size_t)NHEADS * Tq * Dq];
__device__ __align__(128) __half g_v [(size_t)NHEADS * Tq * Dq];
__device__ __align__(128) unsigned char g_mt[NHEADS * Tq];

static __device__ __forceinline__ unsigned packh(float a, float b) {
    __half2 h = __floats2half2_rn(a, b);
    return *reinterpret_cast<unsigned*>(&h);
}
static __device__ __forceinline__ float2 unph(unsigned u) {
    __half2 h = *reinterpret_cast<__half2*>(&u);
    return __half22float2(h);
}
static __device__ __forceinline__ unsigned hmul2u(unsigned a, unsigned b) {
    __half2 r = __hmul2(*reinterpret_cast<__half2*>(&a),
                        *reinterpret_cast<__half2*>(&b));
    return *reinterpret_cast<unsigned*>(&r);
}
static __device__ __forceinline__ void mma_f16_f16(
    unsigned& d0, unsigned& d1,
    unsigned a0, unsigned a1, unsigned a2, unsigned a3,
    unsigned b0, unsigned b1)
{
    asm volatile(
        "mma.sync.aligned.m16n8k16.row.col.f16.f16.f16.f16 "
        "{%0,%1}, {%2,%3,%4,%5}, {%6,%7}, {%0,%1};\n"
        : "+r"(d0), "+r"(d1)
        : "r"(a0), "r"(a1), "r"(a2), "r"(a3), "r"(b0), "r"(b1));
}
static __device__ __forceinline__ void ldsm_x4(
    unsigned& r0, unsigned& r1, unsigned& r2, unsigned& r3, unsigned addr)
{
    asm volatile("ldmatrix.sync.aligned.m8n8.x4.shared.b16 {%0,%1,%2,%3}, [%4];"
        : "=r"(r0), "=r"(r1), "=r"(r2), "=r"(r3) : "r"(addr));
}
static __device__ __forceinline__ void ldsm_x4_t(
    unsigned& r0, unsigned& r1, unsigned& r2, unsigned& r3, unsigned addr)
{
    asm volatile("ldmatrix.sync.aligned.m8n8.x4.trans.shared.b16 {%0,%1,%2,%3}, [%4];"
        : "=r"(r0), "=r"(r1), "=r"(r2), "=r"(r3) : "r"(addr));
}

#define CPA16(d, s) asm volatile("cp.async.cg.shared.global [%0], [%1], 16;" :: "r"(d), "l"(s))
#define CP_COMMIT() asm volatile("cp.async.commit_group;")
#define CP_WAIT(n)  asm volatile("cp.async.wait_group %0;" :: "n"(n))

// ---------------------------------------------------------------------------
__global__ void conv_x_kernel(const float* __restrict__ x)
{
    int i = blockIdx.x * blockDim.x + threadIdx.x;
    const float4 v = ((const float4*)x)[i];
    ((uint2*)g_xb)[i] = make_uint2(packh(v.x, v.y), packh(v.z, v.w));
}
__global__ void conv_w_kernel(const float* __restrict__ wq,
                              const float* __restrict__ wk,
                              const float* __restrict__ wv)
{
    int i = blockIdx.x * blockDim.x + threadIdx.x;
    g_wb[i]          = __float2half(wq[i]);
    g_wb[i + 65536]  = __float2half(wk[i]);
    g_wb[i + 131072] = __float2half(wv[i]);
}
__global__ void conv_m_kernel(const unsigned char* __restrict__ xmask)
{
    int i = blockIdx.x * blockDim.x + threadIdx.x;
    int h = i >> 10, t = i & 1023;
    int b = h >> 4,  c = h & 15;
    g_mt[i] = xmask[(size_t)((b << 10) + t) * Cq + c];
}

// ---------------------------------------------------------------------------
// Persistent-W QKV (R11, unchanged): grid (3, 148), W resident in smem,
// X streamed in double-buffered 128x128 chunks (row stride 272 B).
// ---------------------------------------------------------------------------
#define XB_SZ 34816u
#define PW0_OFF 69632u
#define PW1_OFF 139264u
#define QK_SMEM (139264 + 69632)

__global__ __launch_bounds__(256, 1) void qkv_pers_kernel(
    const int*   __restrict__ pos,
    const float* __restrict__ pe,
    const float* __restrict__ bq,
    const float* __restrict__ bk,
    const float* __restrict__ bv)
{
    extern __shared__ char sm[];
    const unsigned su = (unsigned)__cvta_generic_to_shared(sm);
    const int tid = threadIdx.x, w = tid >> 5, lane = tid & 31;
    const int q = lane & 3, lr = lane >> 2, g = lane >> 3, r8 = lane & 7;
    const int wm = w >> 2, wn = w & 3;
    const int mat = blockIdx.x;
    const int by  = blockIdx.y;

    int nt = 0;
    for (int my = by; my < 512; my += 148) ++nt;
    const int nchunks = 2 * nt;

    const __half* wb = g_wb + mat * 65536;
#pragma unroll
    for (int it = 0; it < 16; ++it) {
        int idx = it * 256 + tid;
        int row = idx >> 4, ch = idx & 15;
        CPA16(su + PW0_OFF + (unsigned)(row * 272 + ch * 16), wb + row * Dq + ch * 8);
        CPA16(su + PW1_OFF + (unsigned)(row * 272 + ch * 16), wb + row * Dq + 128 + ch * 8);
    }
    CP_COMMIT();

    auto issue_x = [&](int ci) {
        const int m0 = (by + (ci >> 1) * 148) << 7;
        const int khalf = ci & 1;
        const unsigned xb_s = su + (unsigned)(ci & 1) * XB_SZ;
        const __half* src = g_xb + (size_t)m0 * Dq + khalf * 128;
#pragma unroll
        for (int it = 0; it < 8; ++it) {
            int idx = it * 256 + tid;
            int row = idx >> 4, ch = idx & 15;
            CPA16(xb_s + (unsigned)(row * 272 + ch * 16), src + row * Dq + ch * 8);
        }
    };
    issue_x(0); CP_COMMIT();
    if (nchunks > 1) { issue_x(1); } CP_COMMIT();

    const float* bias = (mat == 0) ? bq : (mat == 1) ? bk : bv;
    __half* outp = (mat == 0) ? g_q : (mat == 1) ? g_k : g_v;

    const unsigned a_lane = (unsigned)((wm * 64 + (g & 1) * 8 + r8) * 272
                                       + ((g >> 1) * 8) * 2);
    const unsigned b_lane = (unsigned)((wn * 64 + (g >> 1) * 8 + r8) * 272
                                       + ((g & 1) * 8) * 2);

    unsigned acc[4][8][2];

    for (int ci = 0; ci < nchunks; ++ci) {
        CP_WAIT(1);
        __syncthreads();
        const int phase = ci & 1;
        if (phase == 0) {
#pragma unroll
            for (int mt = 0; mt < 4; ++mt)
#pragma unroll
                for (int nt2 = 0; nt2 < 8; ++nt2) { acc[mt][nt2][0] = 0u; acc[mt][nt2][1] = 0u; }
        }
        const unsigned ab = su + (unsigned)(ci & 1) * XB_SZ + a_lane;
        const unsigned bb = su + (phase ? PW1_OFF : PW0_OFF) + b_lane;
#pragma unroll
        for (int kk = 0; kk < 8; ++kk) {
            unsigned af[4][4];
#pragma unroll
            for (int mt = 0; mt < 4; ++mt)
                ldsm_x4(af[mt][0], af[mt][1], af[mt][2], af[mt][3],
                        ab + (unsigned)(mt * 16 * 272) + kk * 32);
#pragma unroll
            for (int nt2 = 0; nt2 < 4; ++nt2) {
                unsigned b0, b1, b2, b3;
                ldsm_x4(b0, b1, b2, b3, bb + (unsigned)(nt2 * 16 * 272) + kk * 32);
#pragma unroll
                for (int mt = 0; mt < 4; ++mt) {
                    mma_f16_f16(acc[mt][2*nt2][0],   acc[mt][2*nt2][1],
                                af[mt][0], af[mt][1], af[mt][2], af[mt][3], b0, b1);
                    mma_f16_f16(acc[mt][2*nt2+1][0], acc[mt][2*nt2+1][1],
                                af[mt][0], af[mt][1], af[mt][2], af[mt][3], b2, b3);
                }
            }
        }
        __syncthreads();
        if (ci + 2 < nchunks) { issue_x(ci + 2); }
        CP_COMMIT();

        if (phase == 1) {
            const int m0 = (by + (ci >> 1) * 148) << 7;
#pragma unroll
            for (int mt = 0; mt < 4; ++mt) {
                const int tokA = m0 + wm * 64 + mt * 16 + lr;
                const int tokB = tokA + 8;
                const int bA = tokA >> 14, tA = (tokA >> 4) & (Tq-1), cA = tokA & (Cq-1);
                const int bB = tokB >> 14, tB = (tokB >> 4) & (Tq-1), cB = tokB & (Cq-1);
                __half* rowA = outp + ((size_t)(bA * Cq + cA) * Tq + tA) * Dq;
                __half* rowB = outp + ((size_t)(bB * Cq + cB) * Tq + tB) * Dq;
                int pA = 0, pB = 0;
                if (mat < 2) { pA = pos[tokA]; pB = pos[tokB]; }
#pragma unroll
                for (int nt2 = 0; nt2 < 8; ++nt2) {
                    const int col = wn * 64 + nt2 * 8 + 2 * q;
                    const float2 b2 = *(const float2*)(bias + col);
                    float2 va = unph(acc[mt][nt2][0]);
                    float2 vb = unph(acc[mt][nt2][1]);
                    float v0 = va.x + b2.x, v1 = va.y + b2.y;
                    float v2 = vb.x + b2.x, v3 = vb.y + b2.y;
                    if (mat < 2) {
                        const float2 csA = *(const float2*)(pe + (size_t)pA * Dq + col);
                        const float2 csB = *(const float2*)(pe + (size_t)pB * Dq + col);
                        float r0 = v0 * csA.x - v1 * csA.y;
                        v1 = v0 * csA.y + v1 * csA.x; v0 = r0;
                        float r2 = v2 * csB.x - v3 * csB.y;
                        v3 = v2 * csB.y + v3 * csB.x; v2 = r2;
                    }
                    *(unsigned*)&rowA[col] = packh(v0, v1);
                    *(unsigned*)&rowB[col] = packh(v2, v3);
                }
            }
        }
    }
}

// ---------------------------------------------------------------------------
// Flash attention, occupancy-2 variant: CTA = (head, 64 q-rows), 128 threads
// (4 warps x 16 rows), K-tile 32, 3-stage cp.async ring, single barrier/iter.
// Same fragment patterns / math as the R6 kernel.
// ---------------------------------------------------------------------------
#define STR 264
#define KTILE 32
#define KB2 (KTILE * STR * 2)      // 16896 (one K or V tile)
#define STG (2 * KB2)              // 33792 per stage
#define QM_OFF (3 * STG)           // 101376
#define KM_OFF (QM_OFF + 64)
#define ATTN_SMEM (KM_OFF + 96 + 32)

__global__ __launch_bounds__(128, 2) void attn_occ2_kernel(
    const float* __restrict__ x,
    const float* __restrict__ lng,
    const float* __restrict__ lnb,
    const float* __restrict__ lsg,
    float* __restrict__ out)
{
    extern __shared__ char smraw[];
    const unsigned char* sQm  = (const unsigned char*)(smraw + QM_OFF);
    const unsigned char* sKmB = (const unsigned char*)(smraw + KM_OFF);
    const unsigned su = (unsigned)__cvta_generic_to_shared(smraw);

    const int tid  = threadIdx.x;
    const int w    = tid >> 5;          // 0..3
    const int lane = tid & 31;
    const int q    = lane & 3;
    const int lr   = lane >> 2;
    const int g    = lane >> 3;
    const int r8   = lane & 7;

    const int h  = blockIdx.y;
    const int b  = h >> 4, c = h & 15;
    const int q0 = blockIdx.x * 64;

    const __half* qg = g_q + ((size_t)h * Tq + q0) * Dq;
    const __half* kg = g_k + (size_t)h * Tq * Dq;
    const __half* vg = g_v + (size_t)h * Tq * Dq;
    const unsigned char* mg = g_mt + h * Tq;

    // ---- stage Q (64x256) into stage-0 region, read frags, release ----
#pragma unroll
    for (int it = 0; it < 16; ++it) {
        int idx = it * 128 + tid;
        int row = idx >> 5, cc = idx & 31;
        CPA16(su + (unsigned)(row * STR * 2 + cc * 16), qg + row * Dq + cc * 8);
    }
    if (tid < 4) CPA16(su + QM_OFF + tid * 16, mg + q0 + tid * 16);
    CP_COMMIT(); CP_WAIT(0);
    __syncthreads();

    unsigned qf[16][4];
    const unsigned qa = su +
        ((unsigned)(w * 16 + (g & 1) * 8 + r8) * STR + (g >> 1) * 8) * 2;
#pragma unroll
    for (int kk = 0; kk < 16; ++kk)
        ldsm_x4(qf[kk][0], qf[kk][1], qf[kk][2], qf[kk][3], qa + kk * 32);
    const int qmA = sQm[w * 16 + lr];
    const int qmB = sQm[w * 16 + lr + 8];
    __syncthreads();

    auto issue = [&](int kt) {
        const int st = kt % 3;
        const unsigned sb = su + st * STG;
        const int k0 = kt * KTILE;
#pragma unroll
        for (int it = 0; it < 8; ++it) {
            int idx = it * 128 + tid;
            int row = idx >> 5, cc = idx & 31;
            CPA16(sb + (unsigned)(row * STR * 2 + cc * 16),
                  kg + (size_t)(k0 + row) * Dq + cc * 8);
            CPA16(sb + KB2 + (unsigned)(row * STR * 2 + cc * 16),
                  vg + (size_t)(k0 + row) * Dq + cc * 8);
        }
        if (tid < 2) CPA16(su + KM_OFF + st * 32 + tid * 16, mg + k0 + tid * 16);
    };
    issue(0); CP_COMMIT();
    issue(1); CP_COMMIT();

    const unsigned koff = ((unsigned)((g >> 1) * 8 + r8) * STR + (g & 1) * 8) * 2;
    const unsigned voff = ((unsigned)((g & 1) * 8 + r8) * STR + (g >> 1) * 8) * 2;

    unsigned oacc[32][2];
#pragma unroll
    for (int j = 0; j < 32; ++j) { oacc[j][0] = 0u; oacc[j][1] = 0u; }
    float mrunA = -CUDART_INF_F, mrunB = -CUDART_INF_F;
    float lsumA = 0.f, lsumB = 0.f;

    for (int kt = 0; kt < 32; ++kt) {
        CP_WAIT(1);
        __syncthreads();
        if (kt + 2 < 32) { issue(kt + 2); }
        CP_COMMIT();

        const int st = kt % 3;
        const unsigned kb_s = su + st * STG;
        const unsigned vb_s = kb_s + KB2;
        const unsigned char* km = sKmB + st * 32;

        // ---- S = Q K^T (f16 accum), 16x32 per warp ----
        unsigned sacc[4][2];
#pragma unroll
        for (int nf = 0; nf < 4; ++nf) { sacc[nf][0] = 0u; sacc[nf][1] = 0u; }
#pragma unroll
        for (int kk = 0; kk < 16; ++kk) {
#pragma unroll
            for (int ng = 0; ng < 2; ++ng) {
                unsigned b0, b1, b2, b3;
                ldsm_x4(b0, b1, b2, b3,
                        kb_s + (unsigned)(ng * 16 * STR * 2) + kk * 32 + koff);
                mma_f16_f16(sacc[2*ng][0],   sacc[2*ng][1],
                            qf[kk][0], qf[kk][1], qf[kk][2], qf[kk][3], b0, b1);
                mma_f16_f16(sacc[2*ng+1][0], sacc[2*ng+1][1],
                            qf[kk][0], qf[kk][1], qf[kk][2], qf[kk][3], b2, b3);
            }
        }

        // ---- mask + scale + row max ----
        float sv[4][4];
        float tmaxA = -CUDART_INF_F, tmaxB = -CUDART_INF_F;
#pragma unroll
        for (int nf = 0; nf < 4; ++nf) {
            const float2 lo = unph(sacc[nf][0]);
            const float2 hi = unph(sacc[nf][1]);
            const int cc = nf * 8 + 2 * q;
            const int k0m = km[cc], k1m = km[cc + 1];
            sv[nf][0] = (qmA | k0m) ? -CUDART_INF_F : lo.x * 0.0625f;
            sv[nf][1] = (qmA | k1m) ? -CUDART_INF_F : lo.y * 0.0625f;
            sv[nf][2] = (qmB | k0m) ? -CUDART_INF_F : hi.x * 0.0625f;
            sv[nf][3] = (qmB | k1m) ? -CUDART_INF_F : hi.y * 0.0625f;
            tmaxA = fmaxf(tmaxA, fmaxf(sv[nf][0], sv[nf][1]));
            tmaxB = fmaxf(tmaxB, fmaxf(sv[nf][2], sv[nf][3]));
        }
        tmaxA = fmaxf(tmaxA, __shfl_xor_sync(0xffffffffu, tmaxA, 1));
        tmaxA = fmaxf(tmaxA, __shfl_xor_sync(0xffffffffu, tmaxA, 2));
        tmaxB = fmaxf(tmaxB, __shfl_xor_sync(0xffffffffu, tmaxB, 1));
        tmaxB = fmaxf(tmaxB, __shfl_xor_sync(0xffffffffu, tmaxB, 2));

        const float mnA = fmaxf(mrunA, tmaxA);
        const float mnB = fmaxf(mrunB, tmaxB);
        const float corrA = (mnA == -CUDART_INF_F) ? 1.f : __expf(mrunA - mnA);
        const float corrB = (mnB == -CUDART_INF_F) ? 1.f : __expf(mrunB - mnB);
        const float mUA = (mnA == -CUDART_INF_F) ? 0.f : mnA;
        const float mUB = (mnB == -CUDART_INF_F) ? 0.f : mnB;
        lsumA *= corrA; lsumB *= corrB;
        mrunA = mnA; mrunB = mnB;

        unsigned pa[2][4];
#pragma unroll
        for (int kk = 0; kk < 2; ++kk) {
            float p00 = __expf(sv[2*kk][0]   - mUA);
            float p01 = __expf(sv[2*kk][1]   - mUA);
            float p02 = __expf(sv[2*kk][2]   - mUB);
            float p03 = __expf(sv[2*kk][3]   - mUB);
            float p10 = __expf(sv[2*kk+1][0] - mUA);
            float p11 = __expf(sv[2*kk+1][1] - mUA);
            float p12 = __expf(sv[2*kk+1][2] - mUB);
            float p13 = __expf(sv[2*kk+1][3] - mUB);
            lsumA += p00 + p01 + p10 + p11;
            lsumB += p02 + p03 + p12 + p13;
            pa[kk][0] = packh(p00, p01);
            pa[kk][1] = packh(p02, p03);
            pa[kk][2] = packh(p10, p11);
            pa[kk][3] = packh(p12, p13);
        }

        const unsigned cA2 = packh(corrA, corrA);
        const unsigned cB2 = packh(corrB, corrB);
#pragma unroll
        for (int j = 0; j < 32; ++j) {
            oacc[j][0] = hmul2u(oacc[j][0], cA2);
            oacc[j][1] = hmul2u(oacc[j][1], cB2);
        }

        // ---- O += P V ----
#pragma unroll
        for (int kk = 0; kk < 2; ++kk) {
#pragma unroll
            for (int dg = 0; dg < 16; ++dg) {
                unsigned v0, v1, v2, v3;
                ldsm_x4_t(v0, v1, v2, v3,
                          vb_s + (unsigned)(kk * 16 * STR * 2) + dg * 32 + voff);
                mma_f16_f16(oacc[2*dg][0],   oacc[2*dg][1],
                            pa[kk][0], pa[kk][1], pa[kk][2], pa[kk][3], v0, v1);
                mma_f16_f16(oacc[2*dg+1][0], oacc[2*dg+1][1],
                            pa[kk][0], pa[kk][1], pa[kk][2], pa[kk][3], v2, v3);
            }
        }
    }

    // ---- epilogue: residual + LayerScale + LayerNorm ----
    lsumA += __shfl_xor_sync(0xffffffffu, lsumA, 1);
    lsumA += __shfl_xor_sync(0xffffffffu, lsumA, 2);
    lsumB += __shfl_xor_sync(0xffffffffu, lsumB, 1);
    lsumB += __shfl_xor_sync(0xffffffffu, lsumB, 2);
    const float invA = (lsumA > 0.f) ? (1.f / lsumA) : 0.f;
    const float invB = (lsumB > 0.f) ? (1.f / lsumB) : 0.f;

    const int gtA = q0 + w * 16 + lr;
    const int gtB = gtA + 8;
    const size_t miA = (size_t)(b * Tq + gtA) * Cq + c;
    const size_t miB = (size_t)(b * Tq + gtB) * Cq + c;
    const float* xA = x + miA * Dq;
    const float* xB = x + miB * Dq;

    float yv[32][4];
    float sumA = 0.f, ssqA = 0.f, sumB = 0.f, ssqB = 0.f;
#pragma unroll
    for (int j = 0; j < 32; ++j) {
        const int cc = j * 8 + 2 * q;
        const float2 g2 = *(const float2*)(lsg + cc);
        const float2 xa = *(const float2*)(xA + cc);
        const float2 xb2 = *(const float2*)(xB + cc);
        const float2 oa = unph(oacc[j][0]);
        const float2 ob = unph(oacc[j][1]);
        float y0 = xa.x  + g2.x * (oa.x * invA);
        float y1 = xa.y  + g2.y * (oa.y * invA);
        float y2 = xb2.x + g2.x * (ob.x * invB);
        float y3 = xb2.y + g2.y * (ob.y * invB);
        yv[j][0] = y0; yv[j][1] = y1; yv[j][2] = y2; yv[j][3] = y3;
        sumA += y0 + y1;  ssqA += y0 * y0 + y1 * y1;
        sumB += y2 + y3;  ssqB += y2 * y2 + y3 * y3;
    }
    sumA += __shfl_xor_sync(0xffffffffu, sumA, 1);
    sumA += __shfl_xor_sync(0xffffffffu, sumA, 2);
    ssqA += __shfl_xor_sync(0xffffffffu, ssqA, 1);
    ssqA += __shfl_xor_sync(0xffffffffu, ssqA, 2);
    sumB += __shfl_xor_sync(0xffffffffu, sumB, 1);
    sumB += __shfl_xor_sync(0xffffffffu, sumB, 2);
    ssqB += __shfl_xor_sync(0xffffffffu, ssqB, 1);
    ssqB += __shfl_xor_sync(0xffffffffu, ssqB, 2);

    const float muA = sumA * (1.f / 256.f);
    const float muB = sumB * (1.f / 256.f);
    const float rsA = rsqrtf(ssqA * (1.f / 256.f) - muA * muA + 1e-5f);
    const float rsB = rsqrtf(ssqB * (1.f / 256.f) - muB * muB + 1e-5f);

    float* oA = out + miA * Dq;
    float* oB = out + miB * Dq;
#pragma unroll
    for (int j = 0; j < 32; ++j) {
        const int cc = j * 8 + 2 * q;
        const float2 gg = *(const float2*)(lng + cc);
        const float2 bb = *(const float2*)(lnb + cc);
        float2 r0, r1;
        r0.x = (yv[j][0] - muA) * rsA * gg.x + bb.x;
        r0.y = (yv[j][1] - muA) * rsA * gg.y + bb.y;
        r1.x = (yv[j][2] - muB) * rsB * gg.x + bb.x;
        r1.y = (yv[j][3] - muB) * rsB * gg.y + bb.y;
        *(float2*)(oA + cc) = r0;
        *(float2*)(oB + cc) = r1;
    }
}

// ---------------------------------------------------------------------------
extern "C" void kernel_launch(void* const* d_in, const int* in_sizes, int n_in,
                              void* d_out, int out_size)
{
    const float* x   = (const float*)d_in[0];
    const unsigned char* xmask = (const unsigned char*)d_in[1];
    const int*   pos = (const int*)d_in[2];
    const float* pe  = (const float*)d_in[3];
    const float* wq  = (const float*)d_in[4];
    const float* bq  = (const float*)d_in[5];
    const float* wk  = (const float*)d_in[6];
    const float* bk  = (const float*)d_in[7];
    const float* wv  = (const float*)d_in[8];
    const float* bv  = (const float*)d_in[9];
    const float* lng = (const float*)d_in[10];
    const float* lnb = (const float*)d_in[11];
    const float* lsg = (const float*)d_in[12];
    float* out = (float*)d_out;

    conv_x_kernel<<<(MTOT * Dq / 4) / 256, 256>>>(x);
    conv_w_kernel<<<(Dq * Dq) / 256, 256>>>(wq, wk, wv);
    conv_m_kernel<<<(NHEADS * Tq) / 256, 256>>>(xmask);

    cudaFuncSetAttribute(qkv_pers_kernel,
                         cudaFuncAttributeMaxDynamicSharedMemorySize, QK_SMEM);
    qkv_pers_kernel<<<dim3(3, 148), 256, QK_SMEM>>>(pos, pe, bq, bk, bv);

    cudaFuncSetAttribute(attn_occ2_kernel,
                         cudaFuncAttributeMaxDynamicSharedMemorySize, ATTN_SMEM);
    attn_occ2_kernel<<<dim3(Tq / 64, NHEADS), 128, ATTN_SMEM>>>(
        x, lng, lnb, lsg, out);
}

// round 13
// speedup vs baseline: 1.2891x; 1.0113x over previous
#include <cuda_runtime.h>
#include <cuda_fp16.h>
#include <math_constants.h>
#include <cstdint>

#define Bq 4
#define Tq 1024
#define Cq 16
#define Dq 256
#define NHEADS (Bq*Cq)
#define MTOT (Bq*Tq*Cq)

__device__ __align__(128) __half g_xb[(size_t)MTOT * Dq];
__device__ __align__(128) __half g_wb[3 * Dq * Dq];
__device__ __align__(128) __half g_q [(size_t)NHEADS * Tq * Dq];
__device__ __align__(128) __half g_k [(size_t)NHEADS * Tq * Dq];
__device__ __align__(128) __half g_v [(size_t)NHEADS * Tq * Dq];
__device__ __align__(128) unsigned char g_mt[NHEADS * Tq];

static __device__ __forceinline__ unsigned packh(float a, float b) {
    __half2 h = __floats2half2_rn(a, b);
    return *reinterpret_cast<unsigned*>(&h);
}
static __device__ __forceinline__ float2 unph(unsigned u) {
    __half2 h = *reinterpret_cast<__half2*>(&u);
    return __half22float2(h);
}
static __device__ __forceinline__ unsigned hmul2u(unsigned a, unsigned b) {
    __half2 r = __hmul2(*reinterpret_cast<__half2*>(&a),
                        *reinterpret_cast<__half2*>(&b));
    return *reinterpret_cast<unsigned*>(&r);
}
static __device__ __forceinline__ void mma_f16_f16(
    unsigned& d0, unsigned& d1,
    unsigned a0, unsigned a1, unsigned a2, unsigned a3,
    unsigned b0, unsigned b1)
{
    asm volatile(
        "mma.sync.aligned.m16n8k16.row.col.f16.f16.f16.f16 "
        "{%0,%1}, {%2,%3,%4,%5}, {%6,%7}, {%0,%1};\n"
        : "+r"(d0), "+r"(d1)
        : "r"(a0), "r"(a1), "r"(a2), "r"(a3), "r"(b0), "r"(b1));
}
static __device__ __forceinline__ void ldsm_x4(
    unsigned& r0, unsigned& r1, unsigned& r2, unsigned& r3, unsigned addr)
{
    asm volatile("ldmatrix.sync.aligned.m8n8.x4.shared.b16 {%0,%1,%2,%3}, [%4];"
        : "=r"(r0), "=r"(r1), "=r"(r2), "=r"(r3) : "r"(addr));
}
static __device__ __forceinline__ void ldsm_x4_t(
    unsigned& r0, unsigned& r1, unsigned& r2, unsigned& r3, unsigned addr)
{
    asm volatile("ldmatrix.sync.aligned.m8n8.x4.trans.shared.b16 {%0,%1,%2,%3}, [%4];"
        : "=r"(r0), "=r"(r1), "=r"(r2), "=r"(r3) : "r"(addr));
}

#define CPA16(d, s) asm volatile("cp.async.cg.shared.global [%0], [%1], 16;" :: "r"(d), "l"(s))
#define CP_COMMIT() asm volatile("cp.async.commit_group;")
#define CP_WAIT(n)  asm volatile("cp.async.wait_group %0;" :: "n"(n))

// ---------------------------------------------------------------------------
__global__ void conv_x_kernel(const float* __restrict__ x)
{
    int i = blockIdx.x * blockDim.x + threadIdx.x;
    const float4 v = ((const float4*)x)[i];
    ((uint2*)g_xb)[i] = make_uint2(packh(v.x, v.y), packh(v.z, v.w));
}
__global__ void conv_w_kernel(const float* __restrict__ wq,
                              const float* __restrict__ wk,
                              const float* __restrict__ wv)
{
    int i = blockIdx.x * blockDim.x + threadIdx.x;
    g_wb[i]          = __float2half(wq[i]);
    g_wb[i + 65536]  = __float2half(wk[i]);
    g_wb[i + 131072] = __float2half(wv[i]);
}
__global__ void conv_m_kernel(const unsigned char* __restrict__ xmask)
{
    int i = blockIdx.x * blockDim.x + threadIdx.x;
    int h = i >> 10, t = i & 1023;
    int b = h >> 4,  c = h & 15;
    g_mt[i] = xmask[(size_t)((b << 10) + t) * Cq + c];
}

// ---------------------------------------------------------------------------
// QKV, occupancy-2: CTA = 64M x 128N (half matrix), 128 threads (2m x 2n
// warps, warp tile 32x64), K=256 in one shot. W resident (67.6KB), X tile
// reloaded per m-tile (2 m-tiles per CTA). 101.4 KB smem -> 2 CTAs/SM.
// ---------------------------------------------------------------------------
#define QW_OFF 0u
#define QX_OFF 67584u
#define QK2_SMEM (67584 + 33792)

__global__ __launch_bounds__(128, 2) void qkv_occ2_kernel(
    const int*   __restrict__ pos,
    const float* __restrict__ pe,
    const float* __restrict__ bq,
    const float* __restrict__ bk,
    const float* __restrict__ bv)
{
    extern __shared__ char sm[];
    const unsigned su = (unsigned)__cvta_generic_to_shared(sm);
    const int tid = threadIdx.x, w = tid >> 5, lane = tid & 31;
    const int q = lane & 3, lr = lane >> 2, g = lane >> 3, r8 = lane & 7;
    const int wm = w >> 1, wn = w & 1;
    const int mat = blockIdx.x >> 1;
    const int n0  = (blockIdx.x & 1) * 128;
    const int m0b = blockIdx.y * 128;          // two 64-row m-tiles

    // ---- load W tile (128 n-rows x 256 k), stride 528 ----
    const __half* wb = g_wb + mat * 65536 + n0 * Dq;
#pragma unroll
    for (int it = 0; it < 32; ++it) {
        int idx = it * 128 + tid;
        int row = idx >> 5, ch = idx & 31;
        CPA16(su + QW_OFF + (unsigned)(row * 528 + ch * 16), wb + row * Dq + ch * 8);
    }
    auto issue_x = [&](int mt) {
        const __half* src = g_xb + (size_t)(m0b + mt * 64) * Dq;
#pragma unroll
        for (int it = 0; it < 16; ++it) {
            int idx = it * 128 + tid;
            int row = idx >> 5, ch = idx & 31;
            CPA16(su + QX_OFF + (unsigned)(row * 528 + ch * 16), src + row * Dq + ch * 8);
        }
    };
    issue_x(0);
    CP_COMMIT();

    const float* bias = (mat == 0) ? bq : (mat == 1) ? bk : bv;
    __half* outp = (mat == 0) ? g_q : (mat == 1) ? g_k : g_v;

    const unsigned a_base = su + QX_OFF +
        (unsigned)((wm * 32 + (g & 1) * 8 + r8) * 528 + ((g >> 1) * 8) * 2);
    const unsigned b_base = su + QW_OFF +
        (unsigned)((wn * 64 + (g >> 1) * 8 + r8) * 528 + ((g & 1) * 8) * 2);

#pragma unroll 1
    for (int mt = 0; mt < 2; ++mt) {
        CP_WAIT(0);
        __syncthreads();

        unsigned acc[2][8][2];
#pragma unroll
        for (int m2 = 0; m2 < 2; ++m2)
#pragma unroll
            for (int nt = 0; nt < 8; ++nt) { acc[m2][nt][0] = 0u; acc[m2][nt][1] = 0u; }

#pragma unroll
        for (int kk = 0; kk < 16; ++kk) {
            unsigned af[2][4];
#pragma unroll
            for (int m2 = 0; m2 < 2; ++m2)
                ldsm_x4(af[m2][0], af[m2][1], af[m2][2], af[m2][3],
                        a_base + (unsigned)(m2 * 16 * 528) + kk * 32);
#pragma unroll
            for (int nt = 0; nt < 4; ++nt) {
                unsigned b0, b1, b2, b3;
                ldsm_x4(b0, b1, b2, b3, b_base + (unsigned)(nt * 16 * 528) + kk * 32);
#pragma unroll
                for (int m2 = 0; m2 < 2; ++m2) {
                    mma_f16_f16(acc[m2][2*nt][0],   acc[m2][2*nt][1],
                                af[m2][0], af[m2][1], af[m2][2], af[m2][3], b0, b1);
                    mma_f16_f16(acc[m2][2*nt+1][0], acc[m2][2*nt+1][1],
                                af[m2][0], af[m2][1], af[m2][2], af[m2][3], b2, b3);
                }
            }
        }
        __syncthreads();
        if (mt == 0) { issue_x(1); }
        CP_COMMIT();

        // ---- epilogue: bias + RoPE + store ----
        const int m0 = m0b + mt * 64;
#pragma unroll
        for (int m2 = 0; m2 < 2; ++m2) {
            const int tokA = m0 + wm * 32 + m2 * 16 + lr;
            const int tokB = tokA + 8;
            const int bA = tokA >> 14, tA = (tokA >> 4) & (Tq-1), cA = tokA & (Cq-1);
            const int bB = tokB >> 14, tB = (tokB >> 4) & (Tq-1), cB = tokB & (Cq-1);
            __half* rowA = outp + ((size_t)(bA * Cq + cA) * Tq + tA) * Dq;
            __half* rowB = outp + ((size_t)(bB * Cq + cB) * Tq + tB) * Dq;
            int pA = 0, pB = 0;
            if (mat < 2) { pA = pos[tokA]; pB = pos[tokB]; }
#pragma unroll
            for (int nt = 0; nt < 8; ++nt) {
                const int col = n0 + wn * 64 + nt * 8 + 2 * q;
                const float2 b2 = *(const float2*)(bias + col);
                float2 va = unph(acc[m2][nt][0]);
                float2 vb = unph(acc[m2][nt][1]);
                float v0 = va.x + b2.x, v1 = va.y + b2.y;
                float v2 = vb.x + b2.x, v3 = vb.y + b2.y;
                if (mat < 2) {
                    const float2 csA = *(const float2*)(pe + (size_t)pA * Dq + col);
                    const float2 csB = *(const float2*)(pe + (size_t)pB * Dq + col);
                    float r0 = v0 * csA.x - v1 * csA.y;
                    v1 = v0 * csA.y + v1 * csA.x; v0 = r0;
                    float r2 = v2 * csB.x - v3 * csB.y;
                    v3 = v2 * csB.y + v3 * csB.x; v2 = r2;
                }
                *(unsigned*)&rowA[col] = packh(v0, v1);
                *(unsigned*)&rowB[col] = packh(v2, v3);
            }
        }
    }
}

// ---------------------------------------------------------------------------
// Flash attention (R12, best-known): occ-2, 4 warps, K-tile 32, 3-stage ring.
// ---------------------------------------------------------------------------
#define STR 264
#define KTILE 32
#define KB2 (KTILE * STR * 2)
#define STG (2 * KB2)
#define QM_OFF (3 * STG)
#define KM_OFF (QM_OFF + 64)
#define ATTN_SMEM (KM_OFF + 96 + 32)

__global__ __launch_bounds__(128, 2) void attn_occ2_kernel(
    const float* __restrict__ x,
    const float* __restrict__ lng,
    const float* __restrict__ lnb,
    const float* __restrict__ lsg,
    float* __restrict__ out)
{
    extern __shared__ char smraw[];
    const unsigned char* sQm  = (const unsigned char*)(smraw + QM_OFF);
    const unsigned char* sKmB = (const unsigned char*)(smraw + KM_OFF);
    const unsigned su = (unsigned)__cvta_generic_to_shared(smraw);

    const int tid  = threadIdx.x;
    const int w    = tid >> 5;
    const int lane = tid & 31;
    const int q    = lane & 3;
    const int lr   = lane >> 2;
    const int g    = lane >> 3;
    const int r8   = lane & 7;

    const int h  = blockIdx.y;
    const int b  = h >> 4, c = h & 15;
    const int q0 = blockIdx.x * 64;

    const __half* qg = g_q + ((size_t)h * Tq + q0) * Dq;
    const __half* kg = g_k + (size_t)h * Tq * Dq;
    const __half* vg = g_v + (size_t)h * Tq * Dq;
    const unsigned char* mg = g_mt + h * Tq;

#pragma unroll
    for (int it = 0; it < 16; ++it) {
        int idx = it * 128 + tid;
        int row = idx >> 5, cc = idx & 31;
        CPA16(su + (unsigned)(row * STR * 2 + cc * 16), qg + row * Dq + cc * 8);
    }
    if (tid < 4) CPA16(su + QM_OFF + tid * 16, mg + q0 + tid * 16);
    CP_COMMIT(); CP_WAIT(0);
    __syncthreads();

    unsigned qf[16][4];
    const unsigned qa = su +
        ((unsigned)(w * 16 + (g & 1) * 8 + r8) * STR + (g >> 1) * 8) * 2;
#pragma unroll
    for (int kk = 0; kk < 16; ++kk)
        ldsm_x4(qf[kk][0], qf[kk][1], qf[kk][2], qf[kk][3], qa + kk * 32);
    const int qmA = sQm[w * 16 + lr];
    const int qmB = sQm[w * 16 + lr + 8];
    __syncthreads();

    auto issue = [&](int kt) {
        const int st = kt % 3;
        const unsigned sb = su + st * STG;
        const int k0 = kt * KTILE;
#pragma unroll
        for (int it = 0; it < 8; ++it) {
            int idx = it * 128 + tid;
            int row = idx >> 5, cc = idx & 31;
            CPA16(sb + (unsigned)(row * STR * 2 + cc * 16),
                  kg + (size_t)(k0 + row) * Dq + cc * 8);
            CPA16(sb + KB2 + (unsigned)(row * STR * 2 + cc * 16),
                  vg + (size_t)(k0 + row) * Dq + cc * 8);
        }
        if (tid < 2) CPA16(su + KM_OFF + st * 32 + tid * 16, mg + k0 + tid * 16);
    };
    issue(0); CP_COMMIT();
    issue(1); CP_COMMIT();

    const unsigned koff = ((unsigned)((g >> 1) * 8 + r8) * STR + (g & 1) * 8) * 2;
    const unsigned voff = ((unsigned)((g & 1) * 8 + r8) * STR + (g >> 1) * 8) * 2;

    unsigned oacc[32][2];
#pragma unroll
    for (int j = 0; j < 32; ++j) { oacc[j][0] = 0u; oacc[j][1] = 0u; }
    float mrunA = -CUDART_INF_F, mrunB = -CUDART_INF_F;
    float lsumA = 0.f, lsumB = 0.f;

    for (int kt = 0; kt < 32; ++kt) {
        CP_WAIT(1);
        __syncthreads();
        if (kt + 2 < 32) { issue(kt + 2); }
        CP_COMMIT();

        const int st = kt % 3;
        const unsigned kb_s = su + st * STG;
        const unsigned vb_s = kb_s + KB2;
        const unsigned char* km = sKmB + st * 32;

        unsigned sacc[4][2];
#pragma unroll
        for (int nf = 0; nf < 4; ++nf) { sacc[nf][0] = 0u; sacc[nf][1] = 0u; }
#pragma unroll
        for (int kk = 0; kk < 16; ++kk) {
#pragma unroll
            for (int ng = 0; ng < 2; ++ng) {
                unsigned b0, b1, b2, b3;
                ldsm_x4(b0, b1, b2, b3,
                        kb_s + (unsigned)(ng * 16 * STR * 2) + kk * 32 + koff);
                mma_f16_f16(sacc[2*ng][0],   sacc[2*ng][1],
                            qf[kk][0], qf[kk][1], qf[kk][2], qf[kk][3], b0, b1);
                mma_f16_f16(sacc[2*ng+1][0], sacc[2*ng+1][1],
                            qf[kk][0], qf[kk][1], qf[kk][2], qf[kk][3], b2, b3);
            }
        }

        float sv[4][4];
        float tmaxA = -CUDART_INF_F, tmaxB = -CUDART_INF_F;
#pragma unroll
        for (int nf = 0; nf < 4; ++nf) {
            const float2 lo = unph(sacc[nf][0]);
            const float2 hi = unph(sacc[nf][1]);
            const int cc = nf * 8 + 2 * q;
            const int k0m = km[cc], k1m = km[cc + 1];
            sv[nf][0] = (qmA | k0m) ? -CUDART_INF_F : lo.x * 0.0625f;
            sv[nf][1] = (qmA | k1m) ? -CUDART_INF_F : lo.y * 0.0625f;
            sv[nf][2] = (qmB | k0m) ? -CUDART_INF_F : hi.x * 0.0625f;
            sv[nf][3] = (qmB | k1m) ? -CUDART_INF_F : hi.y * 0.0625f;
            tmaxA = fmaxf(tmaxA, fmaxf(sv[nf][0], sv[nf][1]));
            tmaxB = fmaxf(tmaxB, fmaxf(sv[nf][2], sv[nf][3]));
        }
        tmaxA = fmaxf(tmaxA, __shfl_xor_sync(0xffffffffu, tmaxA, 1));
        tmaxA = fmaxf(tmaxA, __shfl_xor_sync(0xffffffffu, tmaxA, 2));
        tmaxB = fmaxf(tmaxB, __shfl_xor_sync(0xffffffffu, tmaxB, 1));
        tmaxB = fmaxf(tmaxB, __shfl_xor_sync(0xffffffffu, tmaxB, 2));

        const float mnA = fmaxf(mrunA, tmaxA);
        const float mnB = fmaxf(mrunB, tmaxB);
        const float corrA = (mnA == -CUDART_INF_F) ? 1.f : __expf(mrunA - mnA);
        const float corrB = (mnB == -CUDART_INF_F) ? 1.f : __expf(mrunB - mnB);
        const float mUA = (mnA == -CUDART_INF_F) ? 0.f : mnA;
        const float mUB = (mnB == -CUDART_INF_F) ? 0.f : mnB;
        lsumA *= corrA; lsumB *= corrB;
        mrunA = mnA; mrunB = mnB;

        unsigned pa[2][4];
#pragma unroll
        for (int kk = 0; kk < 2; ++kk) {
            float p00 = __expf(sv[2*kk][0]   - mUA);
            float p01 = __expf(sv[2*kk][1]   - mUA);
            float p02 = __expf(sv[2*kk][2]   - mUB);
            float p03 = __expf(sv[2*kk][3]   - mUB);
            float p10 = __expf(sv[2*kk+1][0] - mUA);
            float p11 = __expf(sv[2*kk+1][1] - mUA);
            float p12 = __expf(sv[2*kk+1][2] - mUB);
            float p13 = __expf(sv[2*kk+1][3] - mUB);
            lsumA += p00 + p01 + p10 + p11;
            lsumB += p02 + p03 + p12 + p13;
            pa[kk][0] = packh(p00, p01);
            pa[kk][1] = packh(p02, p03);
            pa[kk][2] = packh(p10, p11);
            pa[kk][3] = packh(p12, p13);
        }

        const unsigned cA2 = packh(corrA, corrA);
        const unsigned cB2 = packh(corrB, corrB);
#pragma unroll
        for (int j = 0; j < 32; ++j) {
            oacc[j][0] = hmul2u(oacc[j][0], cA2);
            oacc[j][1] = hmul2u(oacc[j][1], cB2);
        }

#pragma unroll
        for (int kk = 0; kk < 2; ++kk) {
#pragma unroll
            for (int dg = 0; dg < 16; ++dg) {
                unsigned v0, v1, v2, v3;
                ldsm_x4_t(v0, v1, v2, v3,
                          vb_s + (unsigned)(kk * 16 * STR * 2) + dg * 32 + voff);
                mma_f16_f16(oacc[2*dg][0],   oacc[2*dg][1],
                            pa[kk][0], pa[kk][1], pa[kk][2], pa[kk][3], v0, v1);
                mma_f16_f16(oacc[2*dg+1][0], oacc[2*dg+1][1],
                            pa[kk][0], pa[kk][1], pa[kk][2], pa[kk][3], v2, v3);
            }
        }
    }

    lsumA += __shfl_xor_sync(0xffffffffu, lsumA, 1);
    lsumA += __shfl_xor_sync(0xffffffffu, lsumA, 2);
    lsumB += __shfl_xor_sync(0xffffffffu, lsumB, 1);
    lsumB += __shfl_xor_sync(0xffffffffu, lsumB, 2);
    const float invA = (lsumA > 0.f) ? (1.f / lsumA) : 0.f;
    const float invB = (lsumB > 0.f) ? (1.f / lsumB) : 0.f;

    const int gtA = q0 + w * 16 + lr;
    const int gtB = gtA + 8;
    const size_t miA = (size_t)(b * Tq + gtA) * Cq + c;
    const size_t miB = (size_t)(b * Tq + gtB) * Cq + c;
    const float* xA = x + miA * Dq;
    const float* xB = x + miB * Dq;

    float yv[32][4];
    float sumA = 0.f, ssqA = 0.f, sumB = 0.f, ssqB = 0.f;
#pragma unroll
    for (int j = 0; j < 32; ++j) {
        const int cc = j * 8 + 2 * q;
        const float2 g2 = *(const float2*)(lsg + cc);
        const float2 xa = *(const float2*)(xA + cc);
        const float2 xb2 = *(const float2*)(xB + cc);
        const float2 oa = unph(oacc[j][0]);
        const float2 ob = unph(oacc[j][1]);
        float y0 = xa.x  + g2.x * (oa.x * invA);
        float y1 = xa.y  + g2.y * (oa.y * invA);
        float y2 = xb2.x + g2.x * (ob.x * invB);
        float y3 = xb2.y + g2.y * (ob.y * invB);
        yv[j][0] = y0; yv[j][1] = y1; yv[j][2] = y2; yv[j][3] = y3;
        sumA += y0 + y1;  ssqA += y0 * y0 + y1 * y1;
        sumB += y2 + y3;  ssqB += y2 * y2 + y3 * y3;
    }
    sumA += __shfl_xor_sync(0xffffffffu, sumA, 1);
    sumA += __shfl_xor_sync(0xffffffffu, sumA, 2);
    ssqA += __shfl_xor_sync(0xffffffffu, ssqA, 1);
    ssqA += __shfl_xor_sync(0xffffffffu, ssqA, 2);
    sumB += __shfl_xor_sync(0xffffffffu, sumB, 1);
    sumB += __shfl_xor_sync(0xffffffffu, sumB, 2);
    ssqB += __shfl_xor_sync(0xffffffffu, ssqB, 1);
    ssqB += __shfl_xor_sync(0xffffffffu, ssqB, 2);

    const float muA = sumA * (1.f / 256.f);
    const float muB = sumB * (1.f / 256.f);
    const float rsA = rsqrtf(ssqA * (1.f / 256.f) - muA * muA + 1e-5f);
    const float rsB = rsqrtf(ssqB * (1.f / 256.f) - muB * muB + 1e-5f);

    float* oA = out + miA * Dq;
    float* oB = out + miB * Dq;
#pragma unroll
    for (int j = 0; j < 32; ++j) {
        const int cc = j * 8 + 2 * q;
        const float2 gg = *(const float2*)(lng + cc);
        const float2 bb = *(const float2*)(lnb + cc);
        float2 r0, r1;
        r0.x = (yv[j][0] - muA) * rsA * gg.x + bb.x;
        r0.y = (yv[j][1] - muA) * rsA * gg.y + bb.y;
        r1.x = (yv[j][2] - muB) * rsB * gg.x + bb.x;
        r1.y = (yv[j][3] - muB) * rsB * gg.y + bb.y;
        *(float2*)(oA + cc) = r0;
        *(float2*)(oB + cc) = r1;
    }
}

// ---------------------------------------------------------------------------
extern "C" void kernel_launch(void* const* d_in, const int* in_sizes, int n_in,
                              void* d_out, int out_size)
{
    const float* x   = (const float*)d_in[0];
    const unsigned char* xmask = (const unsigned char*)d_in[1];
    const int*   pos = (const int*)d_in[2];
    const float* pe  = (const float*)d_in[3];
    const float* wq  = (const float*)d_in[4];
    const float* bq  = (const float*)d_in[5];
    const float* wk  = (const float*)d_in[6];
    const float* bk  = (const float*)d_in[7];
    const float* wv  = (const float*)d_in[8];
    const float* bv  = (const float*)d_in[9];
    const float* lng = (const float*)d_in[10];
    const float* lnb = (const float*)d_in[11];
    const float* lsg = (const float*)d_in[12];
    float* out = (float*)d_out;

    conv_x_kernel<<<(MTOT * Dq / 4) / 256, 256>>>(x);
    conv_w_kernel<<<(Dq * Dq) / 256, 256>>>(wq, wk, wv);
    conv_m_kernel<<<(NHEADS * Tq) / 256, 256>>>(xmask);

    cudaFuncSetAttribute(qkv_occ2_kernel,
                         cudaFuncAttributeMaxDynamicSharedMemorySize, QK2_SMEM);
    qkv_occ2_kernel<<<dim3(6, MTOT / 128), 128, QK2_SMEM>>>(pos, pe, bq, bk, bv);

    cudaFuncSetAttribute(attn_occ2_kernel,
                         cudaFuncAttributeMaxDynamicSharedMemorySize, ATTN_SMEM);
    attn_occ2_kernel<<<dim3(Tq / 64, NHEADS), 128, ATTN_SMEM>>>(
        x, lng, lnb, lsg, out);
}